// round 1
// baseline (speedup 1.0000x reference)
#include <cuda_runtime.h>
#include <math.h>

#define Bc 2
#define Sc 2048
#define Dc 2048
#define Hc 16
#define HDc 128

// Scratch (allocation-free rule: __device__ globals)
__device__ float g_q[Bc*Sc*Dc];
__device__ float g_k[Bc*Sc*Dc];
__device__ float g_v[Bc*Sc*Dc];
__device__ float g_attn[Bc*Sc*Dc];

// ---------------------------------------------------------------------------
// Tiled SGEMM: C[M,N] = A[M,K] @ B[K,N], M=4096, N=K=2048.
// Block tile 128x128, K-tile 16, 256 threads, 8x8 per thread.
// ---------------------------------------------------------------------------
__global__ __launch_bounds__(256) void sgemm128(
    const float* __restrict__ A, const float* __restrict__ Bw,
    float* __restrict__ C)
{
    __shared__ float As[16][132];   // k-major (transposed), pad -> 2-way store conflicts max
    __shared__ float Bs[16][128];

    const int tid  = threadIdx.x;
    const int row0 = blockIdx.y * 128;
    const int col0 = blockIdx.x * 128;
    const int trow = (tid >> 4) << 3;    // 8 rows
    const int tc   = (tid & 15) << 2;    // cols tc..tc+3 and tc+64..tc+67

    float acc[8][8];
    #pragma unroll
    for (int i = 0; i < 8; i++)
        #pragma unroll
        for (int j = 0; j < 8; j++) acc[i][j] = 0.f;

    const int ar = tid >> 2;             // 0..63
    const int ak = (tid & 3) << 2;       // 0,4,8,12
    const int br = tid >> 5;             // 0..7
    const int bcv = (tid & 31) << 2;     // 0..124

    for (int kt = 0; kt < 2048; kt += 16) {
        #pragma unroll
        for (int it = 0; it < 2; it++) {
            int r = ar + it * 64;
            float4 v = *(const float4*)(A + (size_t)(row0 + r) * 2048 + kt + ak);
            As[ak + 0][r] = v.x;
            As[ak + 1][r] = v.y;
            As[ak + 2][r] = v.z;
            As[ak + 3][r] = v.w;
        }
        #pragma unroll
        for (int it = 0; it < 2; it++) {
            int r = br + it * 8;
            *(float4*)&Bs[r][bcv] =
                *(const float4*)(Bw + (size_t)(kt + r) * 2048 + col0 + bcv);
        }
        __syncthreads();

        #pragma unroll
        for (int k = 0; k < 16; k++) {
            float4 a0 = *(float4*)&As[k][trow];
            float4 a1 = *(float4*)&As[k][trow + 4];
            float4 b0 = *(float4*)&Bs[k][tc];
            float4 b1 = *(float4*)&Bs[k][tc + 64];
            float av[8] = {a0.x, a0.y, a0.z, a0.w, a1.x, a1.y, a1.z, a1.w};
            float bv[8] = {b0.x, b0.y, b0.z, b0.w, b1.x, b1.y, b1.z, b1.w};
            #pragma unroll
            for (int i = 0; i < 8; i++)
                #pragma unroll
                for (int j = 0; j < 8; j++)
                    acc[i][j] = fmaf(av[i], bv[j], acc[i][j]);
        }
        __syncthreads();
    }

    #pragma unroll
    for (int i = 0; i < 8; i++) {
        float4 o0 = make_float4(acc[i][0], acc[i][1], acc[i][2], acc[i][3]);
        float4 o1 = make_float4(acc[i][4], acc[i][5], acc[i][6], acc[i][7]);
        float* crow = C + (size_t)(row0 + trow + i) * 2048 + col0;
        *(float4*)(crow + tc)      = o0;
        *(float4*)(crow + tc + 64) = o1;
    }
}

// ---------------------------------------------------------------------------
// RoPE (in place on g_q, g_k). One thread per (token, head, d<64).
// inv_freq computed in f64 (matches numpy), freq rounded to f32 before sincos
// (matches the reference's astype('float32') before np.sin).
// ---------------------------------------------------------------------------
__global__ __launch_bounds__(256) void rope_kernel(const int* __restrict__ pos_ids)
{
    int idx = blockIdx.x * blockDim.x + threadIdx.x;
    if (idx >= Bc * Sc * Hc * (HDc / 2)) return;
    int d = idx & 63;
    int h = (idx >> 6) & (Hc - 1);
    int t = idx >> 10;                       // global token index b*S+s

    double inv = 1.0 / pow(10000.0, (double)(2 * d) / 128.0);
    float f = (float)((double)pos_ids[t] * inv);
    float sn, cs;
    sincosf(f, &sn, &cs);

    size_t base = (size_t)t * Dc + h * HDc + d;
    float q0 = g_q[base], q1 = g_q[base + 64];
    g_q[base]      = q0 * cs - q1 * sn;
    g_q[base + 64] = q1 * cs + q0 * sn;
    float k0 = g_k[base], k1 = g_k[base + 64];
    g_k[base]      = k0 * cs - k1 * sn;
    g_k[base + 64] = k1 * cs + k0 * sn;
}

// ---------------------------------------------------------------------------
// Flash attention, fp32, causal. BQ=BK=64, HD=128, 256 threads (16x16).
// Thread (tx,ty): score rows ty*4+i, score cols tx*4+j,
//                 output rows ty*4+i, output cols {tx*4..+3, 64+tx*4..+3}.
// ---------------------------------------------------------------------------
__global__ __launch_bounds__(256) void flash_kernel(const int* __restrict__ amask)
{
    extern __shared__ float sm[];
    float* Qt = sm;                    // [128][68]  k-major (transposed)
    float* Kt = Qt + 128 * 68;         // [128][68]
    float* Vs = Kt + 128 * 68;         // [64][132]  row-major
    float* Pt = Vs + 64 * 132;         // [64][68]   col-major P (Pt[c][r])

    const int tid = threadIdx.x;
    const int tx = tid & 15, ty = tid >> 4;
    const int qb = blockIdx.x, h = blockIdx.y, b = blockIdx.z;
    const float scale = 0.08838834764831845f;   // 1/sqrt(128)

    // Load Q tile (scaled), transposed into smem
    {
        const float* qsrc = g_q + (size_t)(b * Sc + qb * 64) * Dc + h * HDc;
        #pragma unroll
        for (int it = 0; it < 8; it++) {
            int r  = (tid >> 5) + it * 8;
            int kk = (tid & 31) * 4;
            float4 v = *(const float4*)(qsrc + (size_t)r * Dc + kk);
            Qt[(kk + 0) * 68 + r] = v.x * scale;
            Qt[(kk + 1) * 68 + r] = v.y * scale;
            Qt[(kk + 2) * 68 + r] = v.z * scale;
            Qt[(kk + 3) * 68 + r] = v.w * scale;
        }
    }

    float m[4], l[4], o[4][8];
    #pragma unroll
    for (int i = 0; i < 4; i++) {
        m[i] = -1e30f; l[i] = 0.f;
        #pragma unroll
        for (int j = 0; j < 8; j++) o[i][j] = 0.f;
    }

    for (int kb = 0; kb <= qb; kb++) {
        __syncthreads();   // previous PV done (and Q load visible on first iter)

        const float* ksrc = g_k + (size_t)(b * Sc + kb * 64) * Dc + h * HDc;
        const float* vsrc = g_v + (size_t)(b * Sc + kb * 64) * Dc + h * HDc;
        #pragma unroll
        for (int it = 0; it < 8; it++) {
            int r  = (tid >> 5) + it * 8;
            int kk = (tid & 31) * 4;
            float4 kv = *(const float4*)(ksrc + (size_t)r * Dc + kk);
            Kt[(kk + 0) * 68 + r] = kv.x;
            Kt[(kk + 1) * 68 + r] = kv.y;
            Kt[(kk + 2) * 68 + r] = kv.z;
            Kt[(kk + 3) * 68 + r] = kv.w;
            *(float4*)&Vs[r * 132 + kk] = *(const float4*)(vsrc + (size_t)r * Dc + kk);
        }
        __syncthreads();

        // ---- scores: S = Q K^T (64x64x128) ----
        float s4[4][4];
        #pragma unroll
        for (int i = 0; i < 4; i++)
            #pragma unroll
            for (int j = 0; j < 4; j++) s4[i][j] = 0.f;

        #pragma unroll 16
        for (int kk = 0; kk < 128; kk++) {
            float4 qf = *(float4*)&Qt[kk * 68 + ty * 4];
            float4 kf = *(float4*)&Kt[kk * 68 + tx * 4];
            float qv[4] = {qf.x, qf.y, qf.z, qf.w};
            float kv[4] = {kf.x, kf.y, kf.z, kf.w};
            #pragma unroll
            for (int i = 0; i < 4; i++)
                #pragma unroll
                for (int j = 0; j < 4; j++)
                    s4[i][j] = fmaf(qv[i], kv[j], s4[i][j]);
        }

        // ---- masking (causal on diagonal tile + padding mask) ----
        int mk[4];
        #pragma unroll
        for (int j = 0; j < 4; j++)
            mk[j] = amask[b * Sc + kb * 64 + tx * 4 + j];
        bool diag = (kb == qb);
        #pragma unroll
        for (int i = 0; i < 4; i++)
            #pragma unroll
            for (int j = 0; j < 4; j++) {
                bool dead = (mk[j] == 0) || (diag && (tx * 4 + j) > (ty * 4 + i));
                if (dead) s4[i][j] = -1e30f;
            }

        // ---- online softmax ----
        #pragma unroll
        for (int i = 0; i < 4; i++) {
            float mt = fmaxf(fmaxf(s4[i][0], s4[i][1]), fmaxf(s4[i][2], s4[i][3]));
            #pragma unroll
            for (int off = 1; off < 16; off <<= 1)
                mt = fmaxf(mt, __shfl_xor_sync(0xffffffffu, mt, off));
            float mn  = fmaxf(m[i], mt);
            float fac = __expf(m[i] - mn);
            float p[4], rs = 0.f;
            #pragma unroll
            for (int j = 0; j < 4; j++) {
                p[j] = (s4[i][j] < -5e29f) ? 0.f : __expf(s4[i][j] - mn);
                rs += p[j];
            }
            #pragma unroll
            for (int off = 1; off < 16; off <<= 1)
                rs += __shfl_xor_sync(0xffffffffu, rs, off);
            l[i] = l[i] * fac + rs;
            m[i] = mn;
            #pragma unroll
            for (int jj = 0; jj < 8; jj++) o[i][jj] *= fac;
            #pragma unroll
            for (int j = 0; j < 4; j++)
                Pt[(tx * 4 + j) * 68 + ty * 4 + i] = p[j];
        }
        __syncthreads();

        // ---- O += P V (64x128x64) ----
        #pragma unroll 8
        for (int j = 0; j < 64; j++) {
            float4 pf = *(float4*)&Pt[j * 68 + ty * 4];
            float4 va = *(float4*)&Vs[j * 132 + tx * 4];
            float4 vb = *(float4*)&Vs[j * 132 + tx * 4 + 64];
            float pv[4] = {pf.x, pf.y, pf.z, pf.w};
            #pragma unroll
            for (int i = 0; i < 4; i++) {
                o[i][0] = fmaf(pv[i], va.x, o[i][0]);
                o[i][1] = fmaf(pv[i], va.y, o[i][1]);
                o[i][2] = fmaf(pv[i], va.z, o[i][2]);
                o[i][3] = fmaf(pv[i], va.w, o[i][3]);
                o[i][4] = fmaf(pv[i], vb.x, o[i][4]);
                o[i][5] = fmaf(pv[i], vb.y, o[i][5]);
                o[i][6] = fmaf(pv[i], vb.z, o[i][6]);
                o[i][7] = fmaf(pv[i], vb.w, o[i][7]);
            }
        }
    }

    // ---- epilogue: normalize and store (b, s, h*128+c) layout ----
    float* dst = g_attn + (size_t)(b * Sc + qb * 64) * Dc + h * HDc;
    #pragma unroll
    for (int i = 0; i < 4; i++) {
        float inv = 1.0f / l[i];
        float4 o0 = make_float4(o[i][0] * inv, o[i][1] * inv, o[i][2] * inv, o[i][3] * inv);
        float4 o1 = make_float4(o[i][4] * inv, o[i][5] * inv, o[i][6] * inv, o[i][7] * inv);
        float* row = dst + (size_t)(ty * 4 + i) * Dc;
        *(float4*)(row + tx * 4)      = o0;
        *(float4*)(row + tx * 4 + 64) = o1;
    }
}

// ---------------------------------------------------------------------------
extern "C" void kernel_launch(void* const* d_in, const int* in_sizes, int n_in,
                              void* d_out, int out_size)
{
    const float* X   = (const float*)d_in[0];
    const int*   am  = (const int*)  d_in[1];
    const int*   pos = (const int*)  d_in[2];
    const float* Wq  = (const float*)d_in[3];
    const float* Wk  = (const float*)d_in[4];
    const float* Wv  = (const float*)d_in[5];
    const float* Wo  = (const float*)d_in[6];
    float* out = (float*)d_out;

    float *qp, *kp, *vp, *ap;
    cudaGetSymbolAddress((void**)&qp, g_q);
    cudaGetSymbolAddress((void**)&kp, g_k);
    cudaGetSymbolAddress((void**)&vp, g_v);
    cudaGetSymbolAddress((void**)&ap, g_attn);

    dim3 gg(16, 32), bb(256);
    sgemm128<<<gg, bb>>>(X, Wq, qp);
    sgemm128<<<gg, bb>>>(X, Wk, kp);
    sgemm128<<<gg, bb>>>(X, Wv, vp);

    rope_kernel<<<(Bc * Sc * Hc * (HDc / 2)) / 256, 256>>>(pos);

    const int FLASH_SMEM = (128 * 68 + 128 * 68 + 64 * 132 + 64 * 68) * 4; // 120832 B
    cudaFuncSetAttribute(flash_kernel,
                         cudaFuncAttributeMaxDynamicSharedMemorySize, FLASH_SMEM);
    flash_kernel<<<dim3(32, 16, 2), 256, FLASH_SMEM>>>(am);

    sgemm128<<<gg, bb>>>(ap, Wo, out);
}

// round 3
// speedup vs baseline: 2.5886x; 2.5886x over previous
#include <cuda_runtime.h>
#include <cuda_bf16.h>
#include <math.h>
#include <stdint.h>

#define Bc 2
#define Sc 2048
#define Dc 2048
#define Hc 16
#define HDc 128

// Scratch (allocation-free rule: __device__ globals)
__device__ float g_q[Bc*Sc*Dc];
__device__ float g_k[Bc*Sc*Dc];
__device__ float g_v[Bc*Sc*Dc];
__device__ float g_attn[Bc*Sc*Dc];
__device__ __nv_bfloat16 g_xhi[Bc*Sc*Dc];
__device__ __nv_bfloat16 g_xlo[Bc*Sc*Dc];
__device__ __nv_bfloat16 g_whi[4*Dc*Dc];   // transposed [N][K], 4 weights
__device__ __nv_bfloat16 g_wlo[4*Dc*Dc];

// ---------------------------------------------------------------------------
// PTX helpers (baseline sm_80+ features only — target-portable)
// ---------------------------------------------------------------------------
__device__ __forceinline__ uint32_t smem_u32(const void* p) {
    uint32_t a;
    asm("{ .reg .u64 t; cvta.to.shared.u64 t, %1; cvt.u32.u64 %0, t; }" : "=r"(a) : "l"(p));
    return a;
}
__device__ __forceinline__ void cpasync16(uint32_t dst, const void* src) {
    asm volatile("cp.async.cg.shared.global [%0], [%1], 16;" :: "r"(dst), "l"(src));
}
__device__ __forceinline__ void cp_commit() {
    asm volatile("cp.async.commit_group;" ::: "memory");
}
template <int N>
__device__ __forceinline__ void cp_wait() {
    asm volatile("cp.async.wait_group %0;" :: "n"(N) : "memory");
}
__device__ __forceinline__ void ldsm4(uint32_t& r0, uint32_t& r1, uint32_t& r2,
                                      uint32_t& r3, uint32_t a) {
    asm volatile("ldmatrix.sync.aligned.m8n8.x4.shared.b16 {%0,%1,%2,%3}, [%4];"
                 : "=r"(r0), "=r"(r1), "=r"(r2), "=r"(r3) : "r"(a));
}
__device__ __forceinline__ void ldsm2(uint32_t& r0, uint32_t& r1, uint32_t a) {
    asm volatile("ldmatrix.sync.aligned.m8n8.x2.shared.b16 {%0,%1}, [%2];"
                 : "=r"(r0), "=r"(r1) : "r"(a));
}
__device__ __forceinline__ void mma16816(float* d, const uint32_t* a, const uint32_t* b) {
    asm volatile(
        "mma.sync.aligned.m16n8k16.row.col.f32.bf16.bf16.f32 "
        "{%0,%1,%2,%3}, {%4,%5,%6,%7}, {%8,%9}, {%0,%1,%2,%3};"
        : "+f"(d[0]), "+f"(d[1]), "+f"(d[2]), "+f"(d[3])
        : "r"(a[0]), "r"(a[1]), "r"(a[2]), "r"(a[3]), "r"(b[0]), "r"(b[1]));
}

// ---------------------------------------------------------------------------
// HMMA bf16-split GEMM: C[4096,2048] = A @ W, fp32-class accuracy via
// Ah*Wh + Ah*Wl + Al*Wh (3 bf16 passes, fp32 accum). B pre-transposed [N][K].
// CTA 128x128, K-tile 64, 8 warps (2Mx4N), warp tile 64x32, cp.async double buf.
// Smem row = 64 bf16 = 128B, xor-8 swizzle on 16B units -> conflict-free ldmatrix.
// ---------------------------------------------------------------------------
__global__ __launch_bounds__(256) void gemm_mma(
    const __nv_bfloat16* __restrict__ Ahi, const __nv_bfloat16* __restrict__ Alo,
    const __nv_bfloat16* __restrict__ Bhi, const __nv_bfloat16* __restrict__ Blo,
    float* __restrict__ C)
{
    extern __shared__ __align__(1024) char sm_raw[];
    const uint32_t SMB = smem_u32(sm_raw);   // buf b: A at b*32768, B at +16384

    const int tid  = threadIdx.x;
    const int wid  = tid >> 5, lane = tid & 31;
    const int row0 = blockIdx.y * 128;
    const int col0 = blockIdx.x * 128;

    // loader coords: each thread 4 rows x 16B
    const int lr = tid >> 3;        // 0..31
    const int lc = tid & 7;         // c16 unit 0..7 (k-offset lc*8 bf16)
    uint32_t ldst[4];
    #pragma unroll
    for (int it = 0; it < 4; it++) {
        int r = lr + it * 32;
        ldst[it] = (uint32_t)r * 128u + (uint32_t)((lc ^ (r & 7)) << 4);
    }

    // warp tile
    const int wm = (wid & 1) * 64;
    const int wn = (wid >> 1) * 32;
    // ldmatrix row bases (A: x4, rows = m; B: x2, rows = n)
    const int arow = wm + (lane & 15);
    const int ahi  = lane >> 4;            // 0/1 -> k halves 0/8
    const int brow = wn + (lane & 7);
    const int bhi  = (lane >> 3) & 1;

    float acc[4][4][4];                    // [mf][nf][reg]
    #pragma unroll
    for (int mf = 0; mf < 4; mf++)
        #pragma unroll
        for (int nf = 0; nf < 4; nf++)
            #pragma unroll
            for (int r = 0; r < 4; r++) acc[mf][nf][r] = 0.f;

    // ---- pipeline ----
    auto load_tile = [&](int i) {
        const int b  = i & 1;
        const int s  = i >> 5;
        const int kk = (i & 31) << 6;
        const __nv_bfloat16* As = (s == 2) ? Alo : Ahi;
        const __nv_bfloat16* Bs = (s == 1) ? Blo : Bhi;
        const uint32_t ab = SMB + b * 32768;
        const uint32_t bb = ab + 16384;
        #pragma unroll
        for (int it = 0; it < 4; it++) {
            int r = lr + it * 32;
            cpasync16(ab + ldst[it], As + (size_t)(row0 + r) * 2048 + kk + lc * 8);
            cpasync16(bb + ldst[it], Bs + (size_t)(col0 + r) * 2048 + kk + lc * 8);
        }
        cp_commit();
    };

    load_tile(0);

    #pragma unroll 1
    for (int i = 0; i < 96; i++) {
        if (i + 1 < 96) { load_tile(i + 1); cp_wait<1>(); }
        else            { cp_wait<0>(); }
        __syncthreads();

        const uint32_t ab = SMB + (i & 1) * 32768;
        const uint32_t bb = ab + 16384;

        #pragma unroll
        for (int ks = 0; ks < 4; ks++) {
            uint32_t afr[4][4], bfr[4][2];
            #pragma unroll
            for (int mf = 0; mf < 4; mf++) {
                int r = arow + mf * 16;
                uint32_t addr = ab + (uint32_t)r * 128u
                              + (uint32_t)(((ks * 2 + ahi) ^ (r & 7)) << 4);
                ldsm4(afr[mf][0], afr[mf][1], afr[mf][2], afr[mf][3], addr);
            }
            #pragma unroll
            for (int nf = 0; nf < 4; nf++) {
                int r = brow + nf * 8;
                uint32_t addr = bb + (uint32_t)r * 128u
                              + (uint32_t)(((ks * 2 + bhi) ^ (r & 7)) << 4);
                ldsm2(bfr[nf][0], bfr[nf][1], addr);
            }
            #pragma unroll
            for (int mf = 0; mf < 4; mf++)
                #pragma unroll
                for (int nf = 0; nf < 4; nf++)
                    mma16816(acc[mf][nf], afr[mf], bfr[nf]);
        }
        __syncthreads();
    }

    // ---- epilogue ----
    #pragma unroll
    for (int mf = 0; mf < 4; mf++) {
        int rA = row0 + wm + mf * 16 + (lane >> 2);
        #pragma unroll
        for (int nf = 0; nf < 4; nf++) {
            int cA = col0 + wn + nf * 8 + (lane & 3) * 2;
            float2 lo = make_float2(acc[mf][nf][0], acc[mf][nf][1]);
            float2 hi = make_float2(acc[mf][nf][2], acc[mf][nf][3]);
            *(float2*)(C + (size_t)rA * 2048 + cA)       = lo;
            *(float2*)(C + (size_t)(rA + 8) * 2048 + cA) = hi;
        }
    }
}

// ---------------------------------------------------------------------------
// fp32 -> (bf16 hi, bf16 lo) split, float4 vectorized
// ---------------------------------------------------------------------------
__global__ __launch_bounds__(256) void convert_split(
    const float* __restrict__ src, __nv_bfloat16* __restrict__ hi,
    __nv_bfloat16* __restrict__ lo, int n4)
{
    int idx = blockIdx.x * 256 + threadIdx.x;
    if (idx >= n4) return;
    float4 v = ((const float4*)src)[idx];
    __nv_bfloat16 h0 = __float2bfloat16(v.x), h1 = __float2bfloat16(v.y);
    __nv_bfloat16 h2 = __float2bfloat16(v.z), h3 = __float2bfloat16(v.w);
    __nv_bfloat16 l0 = __float2bfloat16(v.x - __bfloat162float(h0));
    __nv_bfloat16 l1 = __float2bfloat16(v.y - __bfloat162float(h1));
    __nv_bfloat16 l2 = __float2bfloat16(v.z - __bfloat162float(h2));
    __nv_bfloat16 l3 = __float2bfloat16(v.w - __bfloat162float(h3));
    __nv_bfloat162 ph0; ph0.x = h0; ph0.y = h1;
    __nv_bfloat162 ph1; ph1.x = h2; ph1.y = h3;
    __nv_bfloat162 pl0; pl0.x = l0; pl0.y = l1;
    __nv_bfloat162 pl1; pl1.x = l2; pl1.y = l3;
    ((__nv_bfloat162*)hi)[2*idx]   = ph0;
    ((__nv_bfloat162*)hi)[2*idx+1] = ph1;
    ((__nv_bfloat162*)lo)[2*idx]   = pl0;
    ((__nv_bfloat162*)lo)[2*idx+1] = pl1;
}

// ---------------------------------------------------------------------------
// Weight transpose + split: W[K][N] fp32 -> Whi/Wlo[N][K] bf16
// ---------------------------------------------------------------------------
__global__ __launch_bounds__(256) void convert_wt(
    const float* __restrict__ W, __nv_bfloat16* __restrict__ Whi,
    __nv_bfloat16* __restrict__ Wlo)
{
    __shared__ float t[32][33];
    int tx = threadIdx.x, ty = threadIdx.y;
    int kb = blockIdx.y * 32, nb = blockIdx.x * 32;
    #pragma unroll
    for (int it = 0; it < 4; it++)
        t[ty + it * 8][tx] = W[(size_t)(kb + ty + it * 8) * 2048 + nb + tx];
    __syncthreads();
    #pragma unroll
    for (int it = 0; it < 4; it++) {
        float x = t[tx][ty + it * 8];
        __nv_bfloat16 h = __float2bfloat16(x);
        __nv_bfloat16 l = __float2bfloat16(x - __bfloat162float(h));
        size_t o = (size_t)(nb + ty + it * 8) * 2048 + kb + tx;
        Whi[o] = h;
        Wlo[o] = l;
    }
}

// ---------------------------------------------------------------------------
// RoPE (unchanged)
// ---------------------------------------------------------------------------
__global__ __launch_bounds__(256) void rope_kernel(const int* __restrict__ pos_ids)
{
    int idx = blockIdx.x * blockDim.x + threadIdx.x;
    if (idx >= Bc * Sc * Hc * (HDc / 2)) return;
    int d = idx & 63;
    int h = (idx >> 6) & (Hc - 1);
    int t = idx >> 10;

    double inv = 1.0 / pow(10000.0, (double)(2 * d) / 128.0);
    float f = (float)((double)pos_ids[t] * inv);
    float sn, cs;
    sincosf(f, &sn, &cs);

    size_t base = (size_t)t * Dc + h * HDc + d;
    float q0 = g_q[base], q1 = g_q[base + 64];
    g_q[base]      = q0 * cs - q1 * sn;
    g_q[base + 64] = q1 * cs + q0 * sn;
    float k0 = g_k[base], k1 = g_k[base + 64];
    g_k[base]      = k0 * cs - k1 * sn;
    g_k[base + 64] = k1 * cs + k0 * sn;
}

// ---------------------------------------------------------------------------
// Flash attention, fp32, causal (unchanged — known good)
// ---------------------------------------------------------------------------
__global__ __launch_bounds__(256) void flash_kernel(const int* __restrict__ amask)
{
    extern __shared__ float sm[];
    float* Qt = sm;                    // [128][68]
    float* Kt = Qt + 128 * 68;         // [128][68]
    float* Vs = Kt + 128 * 68;         // [64][132]
    float* Pt = Vs + 64 * 132;         // [64][68]

    const int tid = threadIdx.x;
    const int tx = tid & 15, ty = tid >> 4;
    const int qb = blockIdx.x, h = blockIdx.y, b = blockIdx.z;
    const float scale = 0.08838834764831845f;

    {
        const float* qsrc = g_q + (size_t)(b * Sc + qb * 64) * Dc + h * HDc;
        #pragma unroll
        for (int it = 0; it < 8; it++) {
            int r  = (tid >> 5) + it * 8;
            int kk = (tid & 31) * 4;
            float4 v = *(const float4*)(qsrc + (size_t)r * Dc + kk);
            Qt[(kk + 0) * 68 + r] = v.x * scale;
            Qt[(kk + 1) * 68 + r] = v.y * scale;
            Qt[(kk + 2) * 68 + r] = v.z * scale;
            Qt[(kk + 3) * 68 + r] = v.w * scale;
        }
    }

    float m[4], l[4], o[4][8];
    #pragma unroll
    for (int i = 0; i < 4; i++) {
        m[i] = -1e30f; l[i] = 0.f;
        #pragma unroll
        for (int j = 0; j < 8; j++) o[i][j] = 0.f;
    }

    for (int kb = 0; kb <= qb; kb++) {
        __syncthreads();

        const float* ksrc = g_k + (size_t)(b * Sc + kb * 64) * Dc + h * HDc;
        const float* vsrc = g_v + (size_t)(b * Sc + kb * 64) * Dc + h * HDc;
        #pragma unroll
        for (int it = 0; it < 8; it++) {
            int r  = (tid >> 5) + it * 8;
            int kk = (tid & 31) * 4;
            float4 kv = *(const float4*)(ksrc + (size_t)r * Dc + kk);
            Kt[(kk + 0) * 68 + r] = kv.x;
            Kt[(kk + 1) * 68 + r] = kv.y;
            Kt[(kk + 2) * 68 + r] = kv.z;
            Kt[(kk + 3) * 68 + r] = kv.w;
            *(float4*)&Vs[r * 132 + kk] = *(const float4*)(vsrc + (size_t)r * Dc + kk);
        }
        __syncthreads();

        float s4[4][4];
        #pragma unroll
        for (int i = 0; i < 4; i++)
            #pragma unroll
            for (int j = 0; j < 4; j++) s4[i][j] = 0.f;

        #pragma unroll 16
        for (int kk = 0; kk < 128; kk++) {
            float4 qf = *(float4*)&Qt[kk * 68 + ty * 4];
            float4 kf = *(float4*)&Kt[kk * 68 + tx * 4];
            float qv[4] = {qf.x, qf.y, qf.z, qf.w};
            float kv[4] = {kf.x, kf.y, kf.z, kf.w};
            #pragma unroll
            for (int i = 0; i < 4; i++)
                #pragma unroll
                for (int j = 0; j < 4; j++)
                    s4[i][j] = fmaf(qv[i], kv[j], s4[i][j]);
        }

        int mk[4];
        #pragma unroll
        for (int j = 0; j < 4; j++)
            mk[j] = amask[b * Sc + kb * 64 + tx * 4 + j];
        bool diag = (kb == qb);
        #pragma unroll
        for (int i = 0; i < 4; i++)
            #pragma unroll
            for (int j = 0; j < 4; j++) {
                bool dead = (mk[j] == 0) || (diag && (tx * 4 + j) > (ty * 4 + i));
                if (dead) s4[i][j] = -1e30f;
            }

        #pragma unroll
        for (int i = 0; i < 4; i++) {
            float mt = fmaxf(fmaxf(s4[i][0], s4[i][1]), fmaxf(s4[i][2], s4[i][3]));
            #pragma unroll
            for (int off = 1; off < 16; off <<= 1)
                mt = fmaxf(mt, __shfl_xor_sync(0xffffffffu, mt, off));
            float mn  = fmaxf(m[i], mt);
            float fac = __expf(m[i] - mn);
            float p[4], rs = 0.f;
            #pragma unroll
            for (int j = 0; j < 4; j++) {
                p[j] = (s4[i][j] < -5e29f) ? 0.f : __expf(s4[i][j] - mn);
                rs += p[j];
            }
            #pragma unroll
            for (int off = 1; off < 16; off <<= 1)
                rs += __shfl_xor_sync(0xffffffffu, rs, off);
            l[i] = l[i] * fac + rs;
            m[i] = mn;
            #pragma unroll
            for (int jj = 0; jj < 8; jj++) o[i][jj] *= fac;
            #pragma unroll
            for (int j = 0; j < 4; j++)
                Pt[(tx * 4 + j) * 68 + ty * 4 + i] = p[j];
        }
        __syncthreads();

        #pragma unroll 8
        for (int j = 0; j < 64; j++) {
            float4 pf = *(float4*)&Pt[j * 68 + ty * 4];
            float4 va = *(float4*)&Vs[j * 132 + tx * 4];
            float4 vb = *(float4*)&Vs[j * 132 + tx * 4 + 64];
            float pv[4] = {pf.x, pf.y, pf.z, pf.w};
            #pragma unroll
            for (int i = 0; i < 4; i++) {
                o[i][0] = fmaf(pv[i], va.x, o[i][0]);
                o[i][1] = fmaf(pv[i], va.y, o[i][1]);
                o[i][2] = fmaf(pv[i], va.z, o[i][2]);
                o[i][3] = fmaf(pv[i], va.w, o[i][3]);
                o[i][4] = fmaf(pv[i], vb.x, o[i][4]);
                o[i][5] = fmaf(pv[i], vb.y, o[i][5]);
                o[i][6] = fmaf(pv[i], vb.z, o[i][6]);
                o[i][7] = fmaf(pv[i], vb.w, o[i][7]);
            }
        }
    }

    float* dst = g_attn + (size_t)(b * Sc + qb * 64) * Dc + h * HDc;
    #pragma unroll
    for (int i = 0; i < 4; i++) {
        float inv = 1.0f / l[i];
        float4 o0 = make_float4(o[i][0] * inv, o[i][1] * inv, o[i][2] * inv, o[i][3] * inv);
        float4 o1 = make_float4(o[i][4] * inv, o[i][5] * inv, o[i][6] * inv, o[i][7] * inv);
        float* row = dst + (size_t)(ty * 4 + i) * Dc;
        *(float4*)(row + tx * 4)      = o0;
        *(float4*)(row + tx * 4 + 64) = o1;
    }
}

// ---------------------------------------------------------------------------
extern "C" void kernel_launch(void* const* d_in, const int* in_sizes, int n_in,
                              void* d_out, int out_size)
{
    const float* X   = (const float*)d_in[0];
    const int*   am  = (const int*)  d_in[1];
    const int*   pos = (const int*)  d_in[2];
    const float* Wq  = (const float*)d_in[3];
    const float* Wk  = (const float*)d_in[4];
    const float* Wv  = (const float*)d_in[5];
    const float* Wo  = (const float*)d_in[6];
    float* out = (float*)d_out;

    float *qp, *kp, *vp, *ap;
    __nv_bfloat16 *xhi, *xlo, *whi, *wlo;
    cudaGetSymbolAddress((void**)&qp,  g_q);
    cudaGetSymbolAddress((void**)&kp,  g_k);
    cudaGetSymbolAddress((void**)&vp,  g_v);
    cudaGetSymbolAddress((void**)&ap,  g_attn);
    cudaGetSymbolAddress((void**)&xhi, g_xhi);
    cudaGetSymbolAddress((void**)&xlo, g_xlo);
    cudaGetSymbolAddress((void**)&whi, g_whi);
    cudaGetSymbolAddress((void**)&wlo, g_wlo);

    const size_t WSZ = (size_t)Dc * Dc;
    const int N4 = Bc * Sc * Dc / 4;

    convert_split<<<(N4 + 255) / 256, 256>>>(X, xhi, xlo, N4);
    dim3 wtg(64, 64), wtb(32, 8);
    convert_wt<<<wtg, wtb>>>(Wq, whi + 0 * WSZ, wlo + 0 * WSZ);
    convert_wt<<<wtg, wtb>>>(Wk, whi + 1 * WSZ, wlo + 1 * WSZ);
    convert_wt<<<wtg, wtb>>>(Wv, whi + 2 * WSZ, wlo + 2 * WSZ);
    convert_wt<<<wtg, wtb>>>(Wo, whi + 3 * WSZ, wlo + 3 * WSZ);

    const int GEMM_SMEM = 65536;   // 2 x (16KB A + 16KB B)
    cudaFuncSetAttribute(gemm_mma, cudaFuncAttributeMaxDynamicSharedMemorySize, GEMM_SMEM);
    dim3 gg(16, 32), gb(256);
    gemm_mma<<<gg, gb, GEMM_SMEM>>>(xhi, xlo, whi + 0 * WSZ, wlo + 0 * WSZ, qp);
    gemm_mma<<<gg, gb, GEMM_SMEM>>>(xhi, xlo, whi + 1 * WSZ, wlo + 1 * WSZ, kp);
    gemm_mma<<<gg, gb, GEMM_SMEM>>>(xhi, xlo, whi + 2 * WSZ, wlo + 2 * WSZ, vp);

    rope_kernel<<<(Bc * Sc * Hc * (HDc / 2)) / 256, 256>>>(pos);

    const int FLASH_SMEM = (128 * 68 + 128 * 68 + 64 * 132 + 64 * 68) * 4;
    cudaFuncSetAttribute(flash_kernel,
                         cudaFuncAttributeMaxDynamicSharedMemorySize, FLASH_SMEM);
    flash_kernel<<<dim3(32, 16, 2), 256, FLASH_SMEM>>>(am);

    convert_split<<<(N4 + 255) / 256, 256>>>(ap, xhi, xlo, N4);
    gemm_mma<<<gg, gb, GEMM_SMEM>>>(xhi, xlo, whi + 3 * WSZ, wlo + 3 * WSZ, out);
}

// round 4
// speedup vs baseline: 4.0082x; 1.5484x over previous
#include <cuda_runtime.h>
#include <cuda_bf16.h>
#include <math.h>
#include <stdint.h>

#define Bc 2
#define Sc 2048
#define Dc 2048
#define Hc 16
#define HDc 128
#define BQ 128
#define BK 64

// Scratch (allocation-free rule: __device__ globals)
__device__ float g_q[Bc*Sc*Dc];
__device__ float g_k[Bc*Sc*Dc];
__device__ float g_v[Bc*Sc*Dc];
__device__ __nv_bfloat16 g_xhi[Bc*Sc*Dc];
__device__ __nv_bfloat16 g_xlo[Bc*Sc*Dc];
__device__ __nv_bfloat16 g_whi[4*Dc*Dc];   // transposed [N][K], 4 weights
__device__ __nv_bfloat16 g_wlo[4*Dc*Dc];
__device__ __nv_bfloat16 g_qhi[Bc*Sc*Dc];
__device__ __nv_bfloat16 g_qlo[Bc*Sc*Dc];
__device__ __nv_bfloat16 g_khi[Bc*Sc*Dc];
__device__ __nv_bfloat16 g_klo[Bc*Sc*Dc];
__device__ __nv_bfloat16 g_vthi[Bc*Sc*Dc]; // V^T: [b][h][hd][s]
__device__ __nv_bfloat16 g_vtlo[Bc*Sc*Dc];

// ---------------------------------------------------------------------------
// PTX helpers (baseline sm_80+ features only — target-portable)
// ---------------------------------------------------------------------------
__device__ __forceinline__ uint32_t smem_u32(const void* p) {
    uint32_t a;
    asm("{ .reg .u64 t; cvta.to.shared.u64 t, %1; cvt.u32.u64 %0, t; }" : "=r"(a) : "l"(p));
    return a;
}
__device__ __forceinline__ void cpasync16(uint32_t dst, const void* src) {
    asm volatile("cp.async.cg.shared.global [%0], [%1], 16;" :: "r"(dst), "l"(src));
}
__device__ __forceinline__ void cp_commit() {
    asm volatile("cp.async.commit_group;" ::: "memory");
}
template <int N>
__device__ __forceinline__ void cp_wait() {
    asm volatile("cp.async.wait_group %0;" :: "n"(N) : "memory");
}
__device__ __forceinline__ void ldsm4(uint32_t& r0, uint32_t& r1, uint32_t& r2,
                                      uint32_t& r3, uint32_t a) {
    asm volatile("ldmatrix.sync.aligned.m8n8.x4.shared.b16 {%0,%1,%2,%3}, [%4];"
                 : "=r"(r0), "=r"(r1), "=r"(r2), "=r"(r3) : "r"(a));
}
__device__ __forceinline__ void ldsm2(uint32_t& r0, uint32_t& r1, uint32_t a) {
    asm volatile("ldmatrix.sync.aligned.m8n8.x2.shared.b16 {%0,%1}, [%2];"
                 : "=r"(r0), "=r"(r1) : "r"(a));
}
__device__ __forceinline__ void mma16816(float* d, const uint32_t* a, const uint32_t* b) {
    asm volatile(
        "mma.sync.aligned.m16n8k16.row.col.f32.bf16.bf16.f32 "
        "{%0,%1,%2,%3}, {%4,%5,%6,%7}, {%8,%9}, {%0,%1,%2,%3};"
        : "+f"(d[0]), "+f"(d[1]), "+f"(d[2]), "+f"(d[3])
        : "r"(a[0]), "r"(a[1]), "r"(a[2]), "r"(a[3]), "r"(b[0]), "r"(b[1]));
}
// split two floats into packed bf16x2 hi + lo parts
__device__ __forceinline__ void split2(float a, float b, uint32_t& hi, uint32_t& lo) {
    __nv_bfloat16 ha = __float2bfloat16(a), hb = __float2bfloat16(b);
    __nv_bfloat16 la = __float2bfloat16(a - __bfloat162float(ha));
    __nv_bfloat16 lb = __float2bfloat16(b - __bfloat162float(hb));
    __nv_bfloat162 ph; ph.x = ha; ph.y = hb;
    __nv_bfloat162 pl; pl.x = la; pl.y = lb;
    hi = *reinterpret_cast<uint32_t*>(&ph);
    lo = *reinterpret_cast<uint32_t*>(&pl);
}

// ---------------------------------------------------------------------------
// HMMA bf16-split GEMM (unchanged from R3 — 93% of HMMA peak)
// ---------------------------------------------------------------------------
__global__ __launch_bounds__(256) void gemm_mma(
    const __nv_bfloat16* __restrict__ Ahi, const __nv_bfloat16* __restrict__ Alo,
    const __nv_bfloat16* __restrict__ Bhi, const __nv_bfloat16* __restrict__ Blo,
    float* __restrict__ C)
{
    extern __shared__ __align__(1024) char sm_raw[];
    const uint32_t SMB = smem_u32(sm_raw);

    const int tid  = threadIdx.x;
    const int wid  = tid >> 5, lane = tid & 31;
    const int row0 = blockIdx.y * 128;
    const int col0 = blockIdx.x * 128;

    const int lr = tid >> 3;
    const int lc = tid & 7;
    uint32_t ldst[4];
    #pragma unroll
    for (int it = 0; it < 4; it++) {
        int r = lr + it * 32;
        ldst[it] = (uint32_t)r * 128u + (uint32_t)((lc ^ (r & 7)) << 4);
    }

    const int wm = (wid & 1) * 64;
    const int wn = (wid >> 1) * 32;
    const int arow = wm + (lane & 15);
    const int ahi  = lane >> 4;
    const int brow = wn + (lane & 7);
    const int bhi  = (lane >> 3) & 1;

    float acc[4][4][4];
    #pragma unroll
    for (int mf = 0; mf < 4; mf++)
        #pragma unroll
        for (int nf = 0; nf < 4; nf++)
            #pragma unroll
            for (int r = 0; r < 4; r++) acc[mf][nf][r] = 0.f;

    auto load_tile = [&](int i) {
        const int b  = i & 1;
        const int s  = i >> 5;
        const int kk = (i & 31) << 6;
        const __nv_bfloat16* As = (s == 2) ? Alo : Ahi;
        const __nv_bfloat16* Bs = (s == 1) ? Blo : Bhi;
        const uint32_t ab = SMB + b * 32768;
        const uint32_t bb = ab + 16384;
        #pragma unroll
        for (int it = 0; it < 4; it++) {
            int r = lr + it * 32;
            cpasync16(ab + ldst[it], As + (size_t)(row0 + r) * 2048 + kk + lc * 8);
            cpasync16(bb + ldst[it], Bs + (size_t)(col0 + r) * 2048 + kk + lc * 8);
        }
        cp_commit();
    };

    load_tile(0);

    #pragma unroll 1
    for (int i = 0; i < 96; i++) {
        if (i + 1 < 96) { load_tile(i + 1); cp_wait<1>(); }
        else            { cp_wait<0>(); }
        __syncthreads();

        const uint32_t ab = SMB + (i & 1) * 32768;
        const uint32_t bb = ab + 16384;

        #pragma unroll
        for (int ks = 0; ks < 4; ks++) {
            uint32_t afr[4][4], bfr[4][2];
            #pragma unroll
            for (int mf = 0; mf < 4; mf++) {
                int r = arow + mf * 16;
                uint32_t addr = ab + (uint32_t)r * 128u
                              + (uint32_t)(((ks * 2 + ahi) ^ (r & 7)) << 4);
                ldsm4(afr[mf][0], afr[mf][1], afr[mf][2], afr[mf][3], addr);
            }
            #pragma unroll
            for (int nf = 0; nf < 4; nf++) {
                int r = brow + nf * 8;
                uint32_t addr = bb + (uint32_t)r * 128u
                              + (uint32_t)(((ks * 2 + bhi) ^ (r & 7)) << 4);
                ldsm2(bfr[nf][0], bfr[nf][1], addr);
            }
            #pragma unroll
            for (int mf = 0; mf < 4; mf++)
                #pragma unroll
                for (int nf = 0; nf < 4; nf++)
                    mma16816(acc[mf][nf], afr[mf], bfr[nf]);
        }
        __syncthreads();
    }

    #pragma unroll
    for (int mf = 0; mf < 4; mf++) {
        int rA = row0 + wm + mf * 16 + (lane >> 2);
        #pragma unroll
        for (int nf = 0; nf < 4; nf++) {
            int cA = col0 + wn + nf * 8 + (lane & 3) * 2;
            float2 lo = make_float2(acc[mf][nf][0], acc[mf][nf][1]);
            float2 hi = make_float2(acc[mf][nf][2], acc[mf][nf][3]);
            *(float2*)(C + (size_t)rA * 2048 + cA)       = lo;
            *(float2*)(C + (size_t)(rA + 8) * 2048 + cA) = hi;
        }
    }
}

// ---------------------------------------------------------------------------
// fp32 -> (bf16 hi, bf16 lo) split (for X)
// ---------------------------------------------------------------------------
__global__ __launch_bounds__(256) void convert_split(
    const float* __restrict__ src, __nv_bfloat16* __restrict__ hi,
    __nv_bfloat16* __restrict__ lo, int n4)
{
    int idx = blockIdx.x * 256 + threadIdx.x;
    if (idx >= n4) return;
    float4 v = ((const float4*)src)[idx];
    uint32_t h0, l0, h1, l1;
    split2(v.x, v.y, h0, l0);
    split2(v.z, v.w, h1, l1);
    ((uint32_t*)hi)[2*idx]   = h0;
    ((uint32_t*)hi)[2*idx+1] = h1;
    ((uint32_t*)lo)[2*idx]   = l0;
    ((uint32_t*)lo)[2*idx+1] = l1;
}

// ---------------------------------------------------------------------------
// Weight transpose + split: W[K][N] fp32 -> Whi/Wlo[N][K] bf16
// ---------------------------------------------------------------------------
__global__ __launch_bounds__(256) void convert_wt(
    const float* __restrict__ W, __nv_bfloat16* __restrict__ Whi,
    __nv_bfloat16* __restrict__ Wlo)
{
    __shared__ float t[32][33];
    int tx = threadIdx.x, ty = threadIdx.y;
    int kb = blockIdx.y * 32, nb = blockIdx.x * 32;
    #pragma unroll
    for (int it = 0; it < 4; it++)
        t[ty + it * 8][tx] = W[(size_t)(kb + ty + it * 8) * 2048 + nb + tx];
    __syncthreads();
    #pragma unroll
    for (int it = 0; it < 4; it++) {
        float x = t[tx][ty + it * 8];
        __nv_bfloat16 h = __float2bfloat16(x);
        __nv_bfloat16 l = __float2bfloat16(x - __bfloat162float(h));
        size_t o = (size_t)(nb + ty + it * 8) * 2048 + kb + tx;
        Whi[o] = h;
        Wlo[o] = l;
    }
}

// ---------------------------------------------------------------------------
// RoPE + scale(Q by 1/sqrt(HD)*log2e) + bf16 hi/lo split of Q and K
// ---------------------------------------------------------------------------
__global__ __launch_bounds__(256) void rope_split(const int* __restrict__ pos_ids)
{
    int idx = blockIdx.x * 256 + threadIdx.x;
    if (idx >= Bc * Sc * Hc * 64) return;
    int d = idx & 63;
    int h = (idx >> 6) & (Hc - 1);
    int t = idx >> 10;

    double inv = 1.0 / pow(10000.0, (double)(2 * d) / 128.0);
    float f = (float)((double)pos_ids[t] * inv);
    float sn, cs;
    sincosf(f, &sn, &cs);

    const float QS = 0.08838834764831845f * 1.4426950408889634f; // scale * log2(e)
    size_t base = (size_t)t * Dc + h * HDc + d;

    float q0 = g_q[base], q1 = g_q[base + 64];
    float r0 = (q0 * cs - q1 * sn) * QS;
    float r1 = (q1 * cs + q0 * sn) * QS;
    __nv_bfloat16 h0 = __float2bfloat16(r0), h1 = __float2bfloat16(r1);
    g_qhi[base]      = h0;
    g_qhi[base + 64] = h1;
    g_qlo[base]      = __float2bfloat16(r0 - __bfloat162float(h0));
    g_qlo[base + 64] = __float2bfloat16(r1 - __bfloat162float(h1));

    float k0 = g_k[base], k1 = g_k[base + 64];
    float s0 = k0 * cs - k1 * sn;
    float s1 = k1 * cs + k0 * sn;
    __nv_bfloat16 kh0 = __float2bfloat16(s0), kh1 = __float2bfloat16(s1);
    g_khi[base]      = kh0;
    g_khi[base + 64] = kh1;
    g_klo[base]      = __float2bfloat16(s0 - __bfloat162float(kh0));
    g_klo[base + 64] = __float2bfloat16(s1 - __bfloat162float(kh1));
}

// ---------------------------------------------------------------------------
// V transpose + split: g_v [b,s,h,hd] fp32 -> g_vthi/lo [b,h,hd,s] bf16
// ---------------------------------------------------------------------------
__global__ void vt_split()
{
    __shared__ float t[32][33];
    int tx = threadIdx.x, ty = threadIdx.y;
    int s0 = blockIdx.x * 32;
    int d0 = blockIdx.y * 32;
    int bh = blockIdx.z;
    int b = bh >> 4, h = bh & 15;
    #pragma unroll
    for (int it = 0; it < 4; it++)
        t[ty + it * 8][tx] =
            g_v[(size_t)(b * Sc + s0 + ty + it * 8) * Dc + h * HDc + d0 + tx];
    __syncthreads();
    #pragma unroll
    for (int it = 0; it < 4; it++) {
        float x = t[tx][ty + it * 8];
        __nv_bfloat16 hx = __float2bfloat16(x);
        size_t o = (size_t)((b * Hc + h) * HDc + d0 + ty + it * 8) * Sc + s0 + tx;
        g_vthi[o] = hx;
        g_vtlo[o] = __float2bfloat16(x - __bfloat162float(hx));
    }
}

// ---------------------------------------------------------------------------
// HMMA flash attention, causal, bf16 3-way split for QK and PV.
// BQ=128 (8 warps x m16), BK=64. Output written as bf16 hi/lo split to xhi/xlo.
// Smem: Q persistent (2x32KB) + double-buffered K/V tiles (2x64KB) = 192KB.
// ---------------------------------------------------------------------------
__global__ __launch_bounds__(256) void flash_mma(const int* __restrict__ amask)
{
    extern __shared__ char fsm[];
    uint32_t SMB = (smem_u32(fsm) + 1023u) & ~1023u;
    __shared__ int msk[2][64];

    const int tid = threadIdx.x, wid = tid >> 5, lane = tid & 31;
    const int qb = blockIdx.x, h = blockIdx.y, b = blockIdx.z;

    // ---- Q tiles (hi at SMB, lo at SMB+32768): 128 rows x 256B, swizzled ----
    {
        const size_t qoff = (size_t)(b * Sc + qb * BQ) * Dc + h * HDc;
        #pragma unroll
        for (int it = 0; it < 16; it++) {
            int idx = tid + it * 256;           // 0..4095
            int s = idx >> 11;
            int r = (idx >> 4) & 127;
            int u = idx & 15;
            const __nv_bfloat16* src = (s ? g_qlo : g_qhi) + qoff + (size_t)r * Dc + u * 8;
            cpasync16(SMB + s * 32768 + (uint32_t)r * 256 + (uint32_t)((u ^ (r & 7)) << 4), src);
        }
    }
    cp_commit();

    const int nk = 2 * qb + 2;

    auto load_kv = [&](int kb) {
        const uint32_t base = SMB + 65536 + (kb & 1) * 65536;
        const size_t koff = (size_t)(b * Sc + kb * BK) * Dc + h * HDc;
        const size_t voff = (size_t)((b * Hc + h) * HDc) * Sc + kb * BK;
        #pragma unroll
        for (int it = 0; it < 8; it++) {       // K: 64 rows x 16 units x 2 splits
            int idx = tid + it * 256;
            int s = idx >> 10;
            int r = (idx >> 4) & 63;
            int u = idx & 15;
            const __nv_bfloat16* src = (s ? g_klo : g_khi) + koff + (size_t)r * Dc + u * 8;
            cpasync16(base + s * 16384 + (uint32_t)r * 256 + (uint32_t)((u ^ (r & 7)) << 4), src);
        }
        #pragma unroll
        for (int it = 0; it < 8; it++) {       // VT: 128 rows x 8 units x 2 splits
            int idx = tid + it * 256;
            int s = idx >> 10;
            int r = (idx >> 3) & 127;
            int u = idx & 7;
            const __nv_bfloat16* src = (s ? g_vtlo : g_vthi) + voff + (size_t)r * Sc + u * 8;
            cpasync16(base + 32768 + s * 16384 + (uint32_t)r * 128 + (uint32_t)((u ^ (r & 7)) << 4), src);
        }
        if (tid < 64) msk[kb & 1][tid] = amask[b * Sc + kb * BK + tid];
    };

    load_kv(0);
    cp_commit();

    float O[16][4];
    #pragma unroll
    for (int nh = 0; nh < 16; nh++)
        #pragma unroll
        for (int r = 0; r < 4; r++) O[nh][r] = 0.f;
    float m0 = -1e30f, m1 = -1e30f, l0 = 0.f, l1 = 0.f;

    const int wq = wid * 16;
    const int ar = wq + (lane & 15);
    const int ahalf = lane >> 4;
    const int row0g = qb * BQ + wq + (lane >> 2);
    const int qrow_max = qb * BQ + wq + 15;

    #pragma unroll 1
    for (int kb = 0; kb < nk; kb++) {
        if (kb + 1 < nk) { load_kv(kb + 1); cp_commit(); cp_wait<1>(); }
        else             { cp_wait<0>(); }
        __syncthreads();

        const uint32_t kbase = SMB + 65536 + (kb & 1) * 65536;
        const bool active = (kb * BK <= qrow_max);

        if (active) {
            // ---- scores: Q K^T, 3-way split ----
            float S[8][4];
            #pragma unroll
            for (int nf = 0; nf < 8; nf++)
                #pragma unroll
                for (int r = 0; r < 4; r++) S[nf][r] = 0.f;

            #pragma unroll
            for (int ks = 0; ks < 8; ks++) {
                uint32_t ah[4], al[4];
                uint32_t qu = (uint32_t)(((2 * ks + ahalf) ^ (ar & 7)) << 4);
                ldsm4(ah[0], ah[1], ah[2], ah[3], SMB + (uint32_t)ar * 256 + qu);
                ldsm4(al[0], al[1], al[2], al[3], SMB + 32768 + (uint32_t)ar * 256 + qu);
                #pragma unroll
                for (int nf = 0; nf < 8; nf++) {
                    int br = nf * 8 + (lane & 7);
                    uint32_t uo = (uint32_t)(((2 * ks + ((lane >> 3) & 1)) ^ (br & 7)) << 4);
                    uint32_t bh[2], bl[2];
                    ldsm2(bh[0], bh[1], kbase + (uint32_t)br * 256 + uo);
                    ldsm2(bl[0], bl[1], kbase + 16384 + (uint32_t)br * 256 + uo);
                    mma16816(S[nf], ah, bh);
                    mma16816(S[nf], ah, bl);
                    mma16816(S[nf], al, bh);
                }
            }

            // ---- mask (causal + padding) ----
            #pragma unroll
            for (int nf = 0; nf < 8; nf++) {
                int c0 = nf * 8 + (lane & 3) * 2;
                int g0 = kb * BK + c0;
                bool k0 = msk[kb & 1][c0] != 0;
                bool k1 = msk[kb & 1][c0 + 1] != 0;
                if (!k0 || g0     > row0g)     S[nf][0] = -1e30f;
                if (!k1 || g0 + 1 > row0g)     S[nf][1] = -1e30f;
                if (!k0 || g0     > row0g + 8) S[nf][2] = -1e30f;
                if (!k1 || g0 + 1 > row0g + 8) S[nf][3] = -1e30f;
            }

            // ---- online softmax (base-2; log2e folded into Q scale) ----
            float mr0 = -1e30f, mr1 = -1e30f;
            #pragma unroll
            for (int nf = 0; nf < 8; nf++) {
                mr0 = fmaxf(mr0, fmaxf(S[nf][0], S[nf][1]));
                mr1 = fmaxf(mr1, fmaxf(S[nf][2], S[nf][3]));
            }
            mr0 = fmaxf(mr0, __shfl_xor_sync(0xffffffffu, mr0, 1));
            mr0 = fmaxf(mr0, __shfl_xor_sync(0xffffffffu, mr0, 2));
            mr1 = fmaxf(mr1, __shfl_xor_sync(0xffffffffu, mr1, 1));
            mr1 = fmaxf(mr1, __shfl_xor_sync(0xffffffffu, mr1, 2));
            float mn0 = fmaxf(m0, mr0), mn1 = fmaxf(m1, mr1);
            float f0 = exp2f(m0 - mn0), f1 = exp2f(m1 - mn1);

            uint32_t PH[4][4], PL[4][4];
            float rs0 = 0.f, rs1 = 0.f;
            #pragma unroll
            for (int nf = 0; nf < 8; nf++) {
                float p0 = exp2f(S[nf][0] - mn0);
                float p1 = exp2f(S[nf][1] - mn0);
                float p2 = exp2f(S[nf][2] - mn1);
                float p3 = exp2f(S[nf][3] - mn1);
                rs0 += p0 + p1;
                rs1 += p2 + p3;
                int kp = nf >> 1, hv = (nf & 1) * 2;
                split2(p0, p1, PH[kp][hv],     PL[kp][hv]);
                split2(p2, p3, PH[kp][hv + 1], PL[kp][hv + 1]);
            }
            rs0 += __shfl_xor_sync(0xffffffffu, rs0, 1);
            rs0 += __shfl_xor_sync(0xffffffffu, rs0, 2);
            rs1 += __shfl_xor_sync(0xffffffffu, rs1, 1);
            rs1 += __shfl_xor_sync(0xffffffffu, rs1, 2);
            l0 = l0 * f0 + rs0;
            l1 = l1 * f1 + rs1;
            m0 = mn0; m1 = mn1;

            #pragma unroll
            for (int nh = 0; nh < 16; nh++) {
                O[nh][0] *= f0; O[nh][1] *= f0;
                O[nh][2] *= f1; O[nh][3] *= f1;
            }

            // ---- O += P V (3-way split; B frags from pre-transposed V) ----
            const uint32_t vbase = kbase + 32768;
            #pragma unroll
            for (int kp = 0; kp < 4; kp++) {
                #pragma unroll
                for (int nh = 0; nh < 16; nh++) {
                    int vr = nh * 8 + (lane & 7);
                    uint32_t uo = (uint32_t)(((2 * kp + ((lane >> 3) & 1)) ^ (vr & 7)) << 4);
                    uint32_t vh[2], vl[2];
                    ldsm2(vh[0], vh[1], vbase + (uint32_t)vr * 128 + uo);
                    ldsm2(vl[0], vl[1], vbase + 16384 + (uint32_t)vr * 128 + uo);
                    mma16816(O[nh], PH[kp], vh);
                    mma16816(O[nh], PH[kp], vl);
                    mma16816(O[nh], PL[kp], vh);
                }
            }
        }
        __syncthreads();
    }

    // ---- epilogue: normalize, split to bf16 hi/lo, write to xhi/xlo ----
    float i0 = 1.f / l0, i1 = 1.f / l1;
    size_t base0 = (size_t)(b * Sc + row0g) * Dc + h * HDc + (lane & 3) * 2;
    #pragma unroll
    for (int nh = 0; nh < 16; nh++) {
        uint32_t h0, lo0, h1, lo1;
        split2(O[nh][0] * i0, O[nh][1] * i0, h0, lo0);
        split2(O[nh][2] * i1, O[nh][3] * i1, h1, lo1);
        size_t a0 = base0 + nh * 8;
        size_t a1 = a0 + (size_t)8 * Dc;
        *(uint32_t*)(g_xhi + a0) = h0;
        *(uint32_t*)(g_xlo + a0) = lo0;
        *(uint32_t*)(g_xhi + a1) = h1;
        *(uint32_t*)(g_xlo + a1) = lo1;
    }
}

// ---------------------------------------------------------------------------
extern "C" void kernel_launch(void* const* d_in, const int* in_sizes, int n_in,
                              void* d_out, int out_size)
{
    const float* X   = (const float*)d_in[0];
    const int*   am  = (const int*)  d_in[1];
    const int*   pos = (const int*)  d_in[2];
    const float* Wq  = (const float*)d_in[3];
    const float* Wk  = (const float*)d_in[4];
    const float* Wv  = (const float*)d_in[5];
    const float* Wo  = (const float*)d_in[6];
    float* out = (float*)d_out;

    float *qp, *kp, *vp;
    __nv_bfloat16 *xhi, *xlo, *whi, *wlo;
    cudaGetSymbolAddress((void**)&qp,  g_q);
    cudaGetSymbolAddress((void**)&kp,  g_k);
    cudaGetSymbolAddress((void**)&vp,  g_v);
    cudaGetSymbolAddress((void**)&xhi, g_xhi);
    cudaGetSymbolAddress((void**)&xlo, g_xlo);
    cudaGetSymbolAddress((void**)&whi, g_whi);
    cudaGetSymbolAddress((void**)&wlo, g_wlo);

    const size_t WSZ = (size_t)Dc * Dc;
    const int N4 = Bc * Sc * Dc / 4;

    convert_split<<<(N4 + 255) / 256, 256>>>(X, xhi, xlo, N4);
    dim3 wtg(64, 64), wtb(32, 8);
    convert_wt<<<wtg, wtb>>>(Wq, whi + 0 * WSZ, wlo + 0 * WSZ);
    convert_wt<<<wtg, wtb>>>(Wk, whi + 1 * WSZ, wlo + 1 * WSZ);
    convert_wt<<<wtg, wtb>>>(Wv, whi + 2 * WSZ, wlo + 2 * WSZ);
    convert_wt<<<wtg, wtb>>>(Wo, whi + 3 * WSZ, wlo + 3 * WSZ);

    const int GEMM_SMEM = 65536;
    cudaFuncSetAttribute(gemm_mma, cudaFuncAttributeMaxDynamicSharedMemorySize, GEMM_SMEM);
    dim3 gg(16, 32), gb(256);
    gemm_mma<<<gg, gb, GEMM_SMEM>>>(xhi, xlo, whi + 0 * WSZ, wlo + 0 * WSZ, qp);
    gemm_mma<<<gg, gb, GEMM_SMEM>>>(xhi, xlo, whi + 1 * WSZ, wlo + 1 * WSZ, kp);
    gemm_mma<<<gg, gb, GEMM_SMEM>>>(xhi, xlo, whi + 2 * WSZ, wlo + 2 * WSZ, vp);

    rope_split<<<(Bc * Sc * Hc * 64) / 256, 256>>>(pos);
    vt_split<<<dim3(64, 4, 32), dim3(32, 8)>>>();

    const int FLASH_SMEM = 196608 + 1024;
    cudaFuncSetAttribute(flash_mma, cudaFuncAttributeMaxDynamicSharedMemorySize, FLASH_SMEM);
    flash_mma<<<dim3(Sc / BQ, Hc, Bc), 256, FLASH_SMEM>>>(am);

    gemm_mma<<<gg, gb, GEMM_SMEM>>>(xhi, xlo, whi + 3 * WSZ, wlo + 3 * WSZ, out);
}

// round 5
// speedup vs baseline: 4.0192x; 1.0027x over previous
#include <cuda_runtime.h>
#include <cuda_bf16.h>
#include <math.h>
#include <stdint.h>

#define Bc 2
#define Sc 2048
#define Dc 2048
#define Hc 16
#define HDc 128
#define BQ 128
#define BK 64

// Scratch (allocation-free rule: __device__ globals)
__device__ float g_q[Bc*Sc*Dc];
__device__ float g_k[Bc*Sc*Dc];
__device__ float g_v[Bc*Sc*Dc];
__device__ __nv_bfloat16 g_xhi[Bc*Sc*Dc];
__device__ __nv_bfloat16 g_xlo[Bc*Sc*Dc];
__device__ __nv_bfloat16 g_whi[4*Dc*Dc];   // transposed [N][K], 4 weights
__device__ __nv_bfloat16 g_wlo[4*Dc*Dc];
__device__ __nv_bfloat16 g_qhi[Bc*Sc*Dc];
__device__ __nv_bfloat16 g_qlo[Bc*Sc*Dc];
__device__ __nv_bfloat16 g_khi[Bc*Sc*Dc];
__device__ __nv_bfloat16 g_klo[Bc*Sc*Dc];
__device__ __nv_bfloat16 g_vthi[Bc*Sc*Dc]; // V^T: [b][h][hd][s]
__device__ __nv_bfloat16 g_vtlo[Bc*Sc*Dc];

// ---------------------------------------------------------------------------
// PTX helpers (baseline sm_80+ features only — target-portable)
// ---------------------------------------------------------------------------
__device__ __forceinline__ uint32_t smem_u32(const void* p) {
    uint32_t a;
    asm("{ .reg .u64 t; cvta.to.shared.u64 t, %1; cvt.u32.u64 %0, t; }" : "=r"(a) : "l"(p));
    return a;
}
__device__ __forceinline__ void cpasync16(uint32_t dst, const void* src) {
    asm volatile("cp.async.cg.shared.global [%0], [%1], 16;" :: "r"(dst), "l"(src));
}
__device__ __forceinline__ void cp_commit() {
    asm volatile("cp.async.commit_group;" ::: "memory");
}
template <int N>
__device__ __forceinline__ void cp_wait() {
    asm volatile("cp.async.wait_group %0;" :: "n"(N) : "memory");
}
__device__ __forceinline__ void ldsm4(uint32_t& r0, uint32_t& r1, uint32_t& r2,
                                      uint32_t& r3, uint32_t a) {
    asm volatile("ldmatrix.sync.aligned.m8n8.x4.shared.b16 {%0,%1,%2,%3}, [%4];"
                 : "=r"(r0), "=r"(r1), "=r"(r2), "=r"(r3) : "r"(a));
}
__device__ __forceinline__ void ldsm2(uint32_t& r0, uint32_t& r1, uint32_t a) {
    asm volatile("ldmatrix.sync.aligned.m8n8.x2.shared.b16 {%0,%1}, [%2];"
                 : "=r"(r0), "=r"(r1) : "r"(a));
}
__device__ __forceinline__ void mma16816(float* d, const uint32_t* a, const uint32_t* b) {
    asm volatile(
        "mma.sync.aligned.m16n8k16.row.col.f32.bf16.bf16.f32 "
        "{%0,%1,%2,%3}, {%4,%5,%6,%7}, {%8,%9}, {%0,%1,%2,%3};"
        : "+f"(d[0]), "+f"(d[1]), "+f"(d[2]), "+f"(d[3])
        : "r"(a[0]), "r"(a[1]), "r"(a[2]), "r"(a[3]), "r"(b[0]), "r"(b[1]));
}
// split two floats into packed bf16x2 hi + lo parts
__device__ __forceinline__ void split2(float a, float b, uint32_t& hi, uint32_t& lo) {
    __nv_bfloat16 ha = __float2bfloat16(a), hb = __float2bfloat16(b);
    __nv_bfloat16 la = __float2bfloat16(a - __bfloat162float(ha));
    __nv_bfloat16 lb = __float2bfloat16(b - __bfloat162float(hb));
    __nv_bfloat162 ph; ph.x = ha; ph.y = hb;
    __nv_bfloat162 pl; pl.x = la; pl.y = lb;
    hi = *reinterpret_cast<uint32_t*>(&ph);
    lo = *reinterpret_cast<uint32_t*>(&pl);
}

// ---------------------------------------------------------------------------
// HMMA bf16-split GEMM (unchanged — measured at mma.sync peak)
// ---------------------------------------------------------------------------
__global__ __launch_bounds__(256) void gemm_mma(
    const __nv_bfloat16* __restrict__ Ahi, const __nv_bfloat16* __restrict__ Alo,
    const __nv_bfloat16* __restrict__ Bhi, const __nv_bfloat16* __restrict__ Blo,
    float* __restrict__ C)
{
    extern __shared__ __align__(1024) char sm_raw[];
    const uint32_t SMB = smem_u32(sm_raw);

    const int tid  = threadIdx.x;
    const int wid  = tid >> 5, lane = tid & 31;
    const int row0 = blockIdx.y * 128;
    const int col0 = blockIdx.x * 128;

    const int lr = tid >> 3;
    const int lc = tid & 7;
    uint32_t ldst[4];
    #pragma unroll
    for (int it = 0; it < 4; it++) {
        int r = lr + it * 32;
        ldst[it] = (uint32_t)r * 128u + (uint32_t)((lc ^ (r & 7)) << 4);
    }

    const int wm = (wid & 1) * 64;
    const int wn = (wid >> 1) * 32;
    const int arow = wm + (lane & 15);
    const int ahi  = lane >> 4;
    const int brow = wn + (lane & 7);
    const int bhi  = (lane >> 3) & 1;

    float acc[4][4][4];
    #pragma unroll
    for (int mf = 0; mf < 4; mf++)
        #pragma unroll
        for (int nf = 0; nf < 4; nf++)
            #pragma unroll
            for (int r = 0; r < 4; r++) acc[mf][nf][r] = 0.f;

    auto load_tile = [&](int i) {
        const int b  = i & 1;
        const int s  = i >> 5;
        const int kk = (i & 31) << 6;
        const __nv_bfloat16* As = (s == 2) ? Alo : Ahi;
        const __nv_bfloat16* Bs = (s == 1) ? Blo : Bhi;
        const uint32_t ab = SMB + b * 32768;
        const uint32_t bb = ab + 16384;
        #pragma unroll
        for (int it = 0; it < 4; it++) {
            int r = lr + it * 32;
            cpasync16(ab + ldst[it], As + (size_t)(row0 + r) * 2048 + kk + lc * 8);
            cpasync16(bb + ldst[it], Bs + (size_t)(col0 + r) * 2048 + kk + lc * 8);
        }
        cp_commit();
    };

    load_tile(0);

    #pragma unroll 1
    for (int i = 0; i < 96; i++) {
        if (i + 1 < 96) { load_tile(i + 1); cp_wait<1>(); }
        else            { cp_wait<0>(); }
        __syncthreads();

        const uint32_t ab = SMB + (i & 1) * 32768;
        const uint32_t bb = ab + 16384;

        #pragma unroll
        for (int ks = 0; ks < 4; ks++) {
            uint32_t afr[4][4], bfr[4][2];
            #pragma unroll
            for (int mf = 0; mf < 4; mf++) {
                int r = arow + mf * 16;
                uint32_t addr = ab + (uint32_t)r * 128u
                              + (uint32_t)(((ks * 2 + ahi) ^ (r & 7)) << 4);
                ldsm4(afr[mf][0], afr[mf][1], afr[mf][2], afr[mf][3], addr);
            }
            #pragma unroll
            for (int nf = 0; nf < 4; nf++) {
                int r = brow + nf * 8;
                uint32_t addr = bb + (uint32_t)r * 128u
                              + (uint32_t)(((ks * 2 + bhi) ^ (r & 7)) << 4);
                ldsm2(bfr[nf][0], bfr[nf][1], addr);
            }
            #pragma unroll
            for (int mf = 0; mf < 4; mf++)
                #pragma unroll
                for (int nf = 0; nf < 4; nf++)
                    mma16816(acc[mf][nf], afr[mf], bfr[nf]);
        }
        __syncthreads();
    }

    #pragma unroll
    for (int mf = 0; mf < 4; mf++) {
        int rA = row0 + wm + mf * 16 + (lane >> 2);
        #pragma unroll
        for (int nf = 0; nf < 4; nf++) {
            int cA = col0 + wn + nf * 8 + (lane & 3) * 2;
            float2 lo = make_float2(acc[mf][nf][0], acc[mf][nf][1]);
            float2 hi = make_float2(acc[mf][nf][2], acc[mf][nf][3]);
            *(float2*)(C + (size_t)rA * 2048 + cA)       = lo;
            *(float2*)(C + (size_t)(rA + 8) * 2048 + cA) = hi;
        }
    }
}

// ---------------------------------------------------------------------------
// fp32 -> (bf16 hi, bf16 lo) split (for X)
// ---------------------------------------------------------------------------
__global__ __launch_bounds__(256) void convert_split(
    const float* __restrict__ src, __nv_bfloat16* __restrict__ hi,
    __nv_bfloat16* __restrict__ lo, int n4)
{
    int idx = blockIdx.x * 256 + threadIdx.x;
    if (idx >= n4) return;
    float4 v = ((const float4*)src)[idx];
    uint32_t h0, l0, h1, l1;
    split2(v.x, v.y, h0, l0);
    split2(v.z, v.w, h1, l1);
    ((uint32_t*)hi)[2*idx]   = h0;
    ((uint32_t*)hi)[2*idx+1] = h1;
    ((uint32_t*)lo)[2*idx]   = l0;
    ((uint32_t*)lo)[2*idx+1] = l1;
}

// ---------------------------------------------------------------------------
// Weight transpose + split: W[K][N] fp32 -> Whi/Wlo[N][K] bf16
// ---------------------------------------------------------------------------
__global__ __launch_bounds__(256) void convert_wt(
    const float* __restrict__ W, __nv_bfloat16* __restrict__ Whi,
    __nv_bfloat16* __restrict__ Wlo)
{
    __shared__ float t[32][33];
    int tx = threadIdx.x, ty = threadIdx.y;
    int kb = blockIdx.y * 32, nb = blockIdx.x * 32;
    #pragma unroll
    for (int it = 0; it < 4; it++)
        t[ty + it * 8][tx] = W[(size_t)(kb + ty + it * 8) * 2048 + nb + tx];
    __syncthreads();
    #pragma unroll
    for (int it = 0; it < 4; it++) {
        float x = t[tx][ty + it * 8];
        __nv_bfloat16 h = __float2bfloat16(x);
        __nv_bfloat16 l = __float2bfloat16(x - __bfloat162float(h));
        size_t o = (size_t)(nb + ty + it * 8) * 2048 + kb + tx;
        Whi[o] = h;
        Wlo[o] = l;
    }
}

// ---------------------------------------------------------------------------
// RoPE + scale(Q by 1/sqrt(HD)*log2e) + bf16 hi/lo split of Q and K
// ---------------------------------------------------------------------------
__global__ __launch_bounds__(256) void rope_split(const int* __restrict__ pos_ids)
{
    int idx = blockIdx.x * 256 + threadIdx.x;
    if (idx >= Bc * Sc * Hc * 64) return;
    int d = idx & 63;
    int h = (idx >> 6) & (Hc - 1);
    int t = idx >> 10;

    double inv = 1.0 / pow(10000.0, (double)(2 * d) / 128.0);
    float f = (float)((double)pos_ids[t] * inv);
    float sn, cs;
    sincosf(f, &sn, &cs);

    const float QS = 0.08838834764831845f * 1.4426950408889634f; // scale * log2(e)
    size_t base = (size_t)t * Dc + h * HDc + d;

    float q0 = g_q[base], q1 = g_q[base + 64];
    float r0 = (q0 * cs - q1 * sn) * QS;
    float r1 = (q1 * cs + q0 * sn) * QS;
    __nv_bfloat16 h0 = __float2bfloat16(r0), h1 = __float2bfloat16(r1);
    g_qhi[base]      = h0;
    g_qhi[base + 64] = h1;
    g_qlo[base]      = __float2bfloat16(r0 - __bfloat162float(h0));
    g_qlo[base + 64] = __float2bfloat16(r1 - __bfloat162float(h1));

    float k0 = g_k[base], k1 = g_k[base + 64];
    float s0 = k0 * cs - k1 * sn;
    float s1 = k1 * cs + k0 * sn;
    __nv_bfloat16 kh0 = __float2bfloat16(s0), kh1 = __float2bfloat16(s1);
    g_khi[base]      = kh0;
    g_khi[base + 64] = kh1;
    g_klo[base]      = __float2bfloat16(s0 - __bfloat162float(kh0));
    g_klo[base + 64] = __float2bfloat16(s1 - __bfloat162float(kh1));
}

// ---------------------------------------------------------------------------
// V transpose + split: g_v [b,s,h,hd] fp32 -> g_vthi/lo [b,h,hd,s] bf16
// ---------------------------------------------------------------------------
__global__ void vt_split()
{
    __shared__ float t[32][33];
    int tx = threadIdx.x, ty = threadIdx.y;
    int s0 = blockIdx.x * 32;
    int d0 = blockIdx.y * 32;
    int bh = blockIdx.z;
    int b = bh >> 4, h = bh & 15;
    #pragma unroll
    for (int it = 0; it < 4; it++)
        t[ty + it * 8][tx] =
            g_v[(size_t)(b * Sc + s0 + ty + it * 8) * Dc + h * HDc + d0 + tx];
    __syncthreads();
    #pragma unroll
    for (int it = 0; it < 4; it++) {
        float x = t[tx][ty + it * 8];
        __nv_bfloat16 hx = __float2bfloat16(x);
        size_t o = (size_t)((b * Hc + h) * HDc + d0 + ty + it * 8) * Sc + s0 + tx;
        g_vthi[o] = hx;
        g_vtlo[o] = __float2bfloat16(x - __bfloat162float(hx));
    }
}

// ---------------------------------------------------------------------------
// HMMA flash attention, causal, bf16 3-way split for QK and PV.
// BQ=128 (8 warps x m16), BK=64. n-fragments paired into ldsm4 (x4) to clear
// the LDSM issue floor; heavy qb CTAs scheduled first (qb reversed).
// ---------------------------------------------------------------------------
__global__ __launch_bounds__(256) void flash_mma(const int* __restrict__ amask)
{
    extern __shared__ char fsm[];
    uint32_t SMB = (smem_u32(fsm) + 1023u) & ~1023u;
    __shared__ int msk[2][64];

    const int tid = threadIdx.x, wid = tid >> 5, lane = tid & 31;
    const int qb = gridDim.x - 1 - blockIdx.x;   // heavy tiles first
    const int h = blockIdx.y, b = blockIdx.z;

    // ---- Q tiles (hi at SMB, lo at SMB+32768): 128 rows x 256B, swizzled ----
    {
        const size_t qoff = (size_t)(b * Sc + qb * BQ) * Dc + h * HDc;
        #pragma unroll
        for (int it = 0; it < 16; it++) {
            int idx = tid + it * 256;           // 0..4095
            int s = idx >> 11;
            int r = (idx >> 4) & 127;
            int u = idx & 15;
            const __nv_bfloat16* src = (s ? g_qlo : g_qhi) + qoff + (size_t)r * Dc + u * 8;
            cpasync16(SMB + s * 32768 + (uint32_t)r * 256 + (uint32_t)((u ^ (r & 7)) << 4), src);
        }
    }
    cp_commit();

    const int nk = 2 * qb + 2;

    auto load_kv = [&](int kb) {
        const uint32_t base = SMB + 65536 + (kb & 1) * 65536;
        const size_t koff = (size_t)(b * Sc + kb * BK) * Dc + h * HDc;
        const size_t voff = (size_t)((b * Hc + h) * HDc) * Sc + kb * BK;
        #pragma unroll
        for (int it = 0; it < 8; it++) {       // K: 64 rows x 16 units x 2 splits
            int idx = tid + it * 256;
            int s = idx >> 10;
            int r = (idx >> 4) & 63;
            int u = idx & 15;
            const __nv_bfloat16* src = (s ? g_klo : g_khi) + koff + (size_t)r * Dc + u * 8;
            cpasync16(base + s * 16384 + (uint32_t)r * 256 + (uint32_t)((u ^ (r & 7)) << 4), src);
        }
        #pragma unroll
        for (int it = 0; it < 8; it++) {       // VT: 128 rows x 8 units x 2 splits
            int idx = tid + it * 256;
            int s = idx >> 10;
            int r = (idx >> 3) & 127;
            int u = idx & 7;
            const __nv_bfloat16* src = (s ? g_vtlo : g_vthi) + voff + (size_t)r * Sc + u * 8;
            cpasync16(base + 32768 + s * 16384 + (uint32_t)r * 128 + (uint32_t)((u ^ (r & 7)) << 4), src);
        }
        if (tid < 64) msk[kb & 1][tid] = amask[b * Sc + kb * BK + tid];
    };

    load_kv(0);
    cp_commit();

    float O[16][4];
    #pragma unroll
    for (int nh = 0; nh < 16; nh++)
        #pragma unroll
        for (int r = 0; r < 4; r++) O[nh][r] = 0.f;
    float m0 = -1e30f, m1 = -1e30f, l0 = 0.f, l1 = 0.f;

    const int wq = wid * 16;
    const int ar = wq + (lane & 15);
    const int ahalf = lane >> 4;
    // x4 B-fragment lane map: lanes 0-15 -> n rows 0-7 (k lo/hi), 16-31 -> n rows 8-15
    const int brr   = (lane & 7) | ((lane & 16) >> 1);
    const int bhalf = (lane >> 3) & 1;
    const int row0g = qb * BQ + wq + (lane >> 2);
    const int qrow_max = qb * BQ + wq + 15;

    #pragma unroll 1
    for (int kb = 0; kb < nk; kb++) {
        if (kb + 1 < nk) { load_kv(kb + 1); cp_commit(); cp_wait<1>(); }
        else             { cp_wait<0>(); }
        __syncthreads();

        const uint32_t kbase = SMB + 65536 + (kb & 1) * 65536;
        const bool active = (kb * BK <= qrow_max);

        if (active) {
            // ---- scores: Q K^T, 3-way split, paired-n ldsm4 B frags ----
            float S[8][4];
            #pragma unroll
            for (int nf = 0; nf < 8; nf++)
                #pragma unroll
                for (int r = 0; r < 4; r++) S[nf][r] = 0.f;

            #pragma unroll
            for (int ks = 0; ks < 8; ks++) {
                uint32_t ah[4], al[4];
                uint32_t qu = (uint32_t)(((2 * ks + ahalf) ^ (ar & 7)) << 4);
                ldsm4(ah[0], ah[1], ah[2], ah[3], SMB + (uint32_t)ar * 256 + qu);
                ldsm4(al[0], al[1], al[2], al[3], SMB + 32768 + (uint32_t)ar * 256 + qu);
                #pragma unroll
                for (int np = 0; np < 4; np++) {
                    int r = np * 16 + brr;
                    uint32_t uo = (uint32_t)(((2 * ks + bhalf) ^ (r & 7)) << 4);
                    uint32_t bh[4], bl[4];
                    ldsm4(bh[0], bh[1], bh[2], bh[3], kbase + (uint32_t)r * 256 + uo);
                    ldsm4(bl[0], bl[1], bl[2], bl[3], kbase + 16384 + (uint32_t)r * 256 + uo);
                    mma16816(S[2*np],     ah, bh + 0);
                    mma16816(S[2*np + 1], ah, bh + 2);
                    mma16816(S[2*np],     ah, bl + 0);
                    mma16816(S[2*np + 1], ah, bl + 2);
                    mma16816(S[2*np],     al, bh + 0);
                    mma16816(S[2*np + 1], al, bh + 2);
                }
            }

            // ---- mask (causal + padding) ----
            #pragma unroll
            for (int nf = 0; nf < 8; nf++) {
                int c0 = nf * 8 + (lane & 3) * 2;
                int g0 = kb * BK + c0;
                bool k0 = msk[kb & 1][c0] != 0;
                bool k1 = msk[kb & 1][c0 + 1] != 0;
                if (!k0 || g0     > row0g)     S[nf][0] = -1e30f;
                if (!k1 || g0 + 1 > row0g)     S[nf][1] = -1e30f;
                if (!k0 || g0     > row0g + 8) S[nf][2] = -1e30f;
                if (!k1 || g0 + 1 > row0g + 8) S[nf][3] = -1e30f;
            }

            // ---- online softmax (base-2; log2e folded into Q scale) ----
            float mr0 = -1e30f, mr1 = -1e30f;
            #pragma unroll
            for (int nf = 0; nf < 8; nf++) {
                mr0 = fmaxf(mr0, fmaxf(S[nf][0], S[nf][1]));
                mr1 = fmaxf(mr1, fmaxf(S[nf][2], S[nf][3]));
            }
            mr0 = fmaxf(mr0, __shfl_xor_sync(0xffffffffu, mr0, 1));
            mr0 = fmaxf(mr0, __shfl_xor_sync(0xffffffffu, mr0, 2));
            mr1 = fmaxf(mr1, __shfl_xor_sync(0xffffffffu, mr1, 1));
            mr1 = fmaxf(mr1, __shfl_xor_sync(0xffffffffu, mr1, 2));
            float mn0 = fmaxf(m0, mr0), mn1 = fmaxf(m1, mr1);
            float f0 = exp2f(m0 - mn0), f1 = exp2f(m1 - mn1);

            uint32_t PH[4][4], PL[4][4];
            float rs0 = 0.f, rs1 = 0.f;
            #pragma unroll
            for (int nf = 0; nf < 8; nf++) {
                float p0 = exp2f(S[nf][0] - mn0);
                float p1 = exp2f(S[nf][1] - mn0);
                float p2 = exp2f(S[nf][2] - mn1);
                float p3 = exp2f(S[nf][3] - mn1);
                rs0 += p0 + p1;
                rs1 += p2 + p3;
                int kp = nf >> 1, hv = (nf & 1) * 2;
                split2(p0, p1, PH[kp][hv],     PL[kp][hv]);
                split2(p2, p3, PH[kp][hv + 1], PL[kp][hv + 1]);
            }
            rs0 += __shfl_xor_sync(0xffffffffu, rs0, 1);
            rs0 += __shfl_xor_sync(0xffffffffu, rs0, 2);
            rs1 += __shfl_xor_sync(0xffffffffu, rs1, 1);
            rs1 += __shfl_xor_sync(0xffffffffu, rs1, 2);
            l0 = l0 * f0 + rs0;
            l1 = l1 * f1 + rs1;
            m0 = mn0; m1 = mn1;

            #pragma unroll
            for (int nh = 0; nh < 16; nh++) {
                O[nh][0] *= f0; O[nh][1] *= f0;
                O[nh][2] *= f1; O[nh][3] *= f1;
            }

            // ---- O += P V (3-way split; paired-n ldsm4 V frags) ----
            const uint32_t vbase = kbase + 32768;
            #pragma unroll
            for (int kp = 0; kp < 4; kp++) {
                #pragma unroll
                for (int nhp = 0; nhp < 8; nhp++) {
                    int r = nhp * 16 + brr;
                    uint32_t uo = (uint32_t)(((2 * kp + bhalf) ^ (r & 7)) << 4);
                    uint32_t vh[4], vl[4];
                    ldsm4(vh[0], vh[1], vh[2], vh[3], vbase + (uint32_t)r * 128 + uo);
                    ldsm4(vl[0], vl[1], vl[2], vl[3], vbase + 16384 + (uint32_t)r * 128 + uo);
                    mma16816(O[2*nhp],     PH[kp], vh + 0);
                    mma16816(O[2*nhp + 1], PH[kp], vh + 2);
                    mma16816(O[2*nhp],     PH[kp], vl + 0);
                    mma16816(O[2*nhp + 1], PH[kp], vl + 2);
                    mma16816(O[2*nhp],     PL[kp], vh + 0);
                    mma16816(O[2*nhp + 1], PL[kp], vh + 2);
                }
            }
        }
        __syncthreads();
    }

    // ---- epilogue: normalize, split to bf16 hi/lo, write to xhi/xlo ----
    float i0 = 1.f / l0, i1 = 1.f / l1;
    size_t base0 = (size_t)(b * Sc + row0g) * Dc + h * HDc + (lane & 3) * 2;
    #pragma unroll
    for (int nh = 0; nh < 16; nh++) {
        uint32_t h0, lo0, h1, lo1;
        split2(O[nh][0] * i0, O[nh][1] * i0, h0, lo0);
        split2(O[nh][2] * i1, O[nh][3] * i1, h1, lo1);
        size_t a0 = base0 + nh * 8;
        size_t a1 = a0 + (size_t)8 * Dc;
        *(uint32_t*)(g_xhi + a0) = h0;
        *(uint32_t*)(g_xlo + a0) = lo0;
        *(uint32_t*)(g_xhi + a1) = h1;
        *(uint32_t*)(g_xlo + a1) = lo1;
    }
}

// ---------------------------------------------------------------------------
extern "C" void kernel_launch(void* const* d_in, const int* in_sizes, int n_in,
                              void* d_out, int out_size)
{
    const float* X   = (const float*)d_in[0];
    const int*   am  = (const int*)  d_in[1];
    const int*   pos = (const int*)  d_in[2];
    const float* Wq  = (const float*)d_in[3];
    const float* Wk  = (const float*)d_in[4];
    const float* Wv  = (const float*)d_in[5];
    const float* Wo  = (const float*)d_in[6];
    float* out = (float*)d_out;

    float *qp, *kp, *vp;
    __nv_bfloat16 *xhi, *xlo, *whi, *wlo;
    cudaGetSymbolAddress((void**)&qp,  g_q);
    cudaGetSymbolAddress((void**)&kp,  g_k);
    cudaGetSymbolAddress((void**)&vp,  g_v);
    cudaGetSymbolAddress((void**)&xhi, g_xhi);
    cudaGetSymbolAddress((void**)&xlo, g_xlo);
    cudaGetSymbolAddress((void**)&whi, g_whi);
    cudaGetSymbolAddress((void**)&wlo, g_wlo);

    const size_t WSZ = (size_t)Dc * Dc;
    const int N4 = Bc * Sc * Dc / 4;

    convert_split<<<(N4 + 255) / 256, 256>>>(X, xhi, xlo, N4);
    dim3 wtg(64, 64), wtb(32, 8);
    convert_wt<<<wtg, wtb>>>(Wq, whi + 0 * WSZ, wlo + 0 * WSZ);
    convert_wt<<<wtg, wtb>>>(Wk, whi + 1 * WSZ, wlo + 1 * WSZ);
    convert_wt<<<wtg, wtb>>>(Wv, whi + 2 * WSZ, wlo + 2 * WSZ);
    convert_wt<<<wtg, wtb>>>(Wo, whi + 3 * WSZ, wlo + 3 * WSZ);

    const int GEMM_SMEM = 65536;
    cudaFuncSetAttribute(gemm_mma, cudaFuncAttributeMaxDynamicSharedMemorySize, GEMM_SMEM);
    dim3 gg(16, 32), gb(256);
    gemm_mma<<<gg, gb, GEMM_SMEM>>>(xhi, xlo, whi + 0 * WSZ, wlo + 0 * WSZ, qp);
    gemm_mma<<<gg, gb, GEMM_SMEM>>>(xhi, xlo, whi + 1 * WSZ, wlo + 1 * WSZ, kp);
    gemm_mma<<<gg, gb, GEMM_SMEM>>>(xhi, xlo, whi + 2 * WSZ, wlo + 2 * WSZ, vp);

    rope_split<<<(Bc * Sc * Hc * 64) / 256, 256>>>(pos);
    vt_split<<<dim3(64, 4, 32), dim3(32, 8)>>>();

    const int FLASH_SMEM = 196608 + 1024;
    cudaFuncSetAttribute(flash_mma, cudaFuncAttributeMaxDynamicSharedMemorySize, FLASH_SMEM);
    flash_mma<<<dim3(Sc / BQ, Hc, Bc), 256, FLASH_SMEM>>>(am);

    gemm_mma<<<gg, gb, GEMM_SMEM>>>(xhi, xlo, whi + 3 * WSZ, wlo + 3 * WSZ, out);
}

// round 6
// speedup vs baseline: 4.2393x; 1.0548x over previous
#include <cuda_runtime.h>
#include <cuda_bf16.h>
#include <cuda_fp16.h>
#include <math.h>
#include <stdint.h>

#define Bc 2
#define Sc 2048
#define Dc 2048
#define Hc 16
#define HDc 128
#define BQ 64
#define BK 64

// Scratch (allocation-free rule: __device__ globals)
__device__ float g_q[Bc*Sc*Dc];
__device__ float g_k[Bc*Sc*Dc];
__device__ float g_v[Bc*Sc*Dc];
__device__ __nv_bfloat16 g_xhi[Bc*Sc*Dc];
__device__ __nv_bfloat16 g_xlo[Bc*Sc*Dc];
__device__ __nv_bfloat16 g_whi[4*Dc*Dc];   // transposed [N][K], 4 weights
__device__ __nv_bfloat16 g_wlo[4*Dc*Dc];
__device__ __nv_bfloat16 g_qhi[Bc*Sc*Dc];
__device__ __nv_bfloat16 g_qlo[Bc*Sc*Dc];
__device__ __nv_bfloat16 g_khi[Bc*Sc*Dc];
__device__ __nv_bfloat16 g_klo[Bc*Sc*Dc];
__device__ __half g_vth[Bc*Sc*Dc];          // V^T fp16: [b][h][hd][s]

// ---------------------------------------------------------------------------
// PTX helpers (baseline sm_80+ features only — target-portable)
// ---------------------------------------------------------------------------
__device__ __forceinline__ uint32_t smem_u32(const void* p) {
    uint32_t a;
    asm("{ .reg .u64 t; cvta.to.shared.u64 t, %1; cvt.u32.u64 %0, t; }" : "=r"(a) : "l"(p));
    return a;
}
__device__ __forceinline__ void cpasync16(uint32_t dst, const void* src) {
    asm volatile("cp.async.cg.shared.global [%0], [%1], 16;" :: "r"(dst), "l"(src));
}
__device__ __forceinline__ void cp_commit() {
    asm volatile("cp.async.commit_group;" ::: "memory");
}
template <int N>
__device__ __forceinline__ void cp_wait() {
    asm volatile("cp.async.wait_group %0;" :: "n"(N) : "memory");
}
__device__ __forceinline__ void ldsm4(uint32_t& r0, uint32_t& r1, uint32_t& r2,
                                      uint32_t& r3, uint32_t a) {
    asm volatile("ldmatrix.sync.aligned.m8n8.x4.shared.b16 {%0,%1,%2,%3}, [%4];"
                 : "=r"(r0), "=r"(r1), "=r"(r2), "=r"(r3) : "r"(a));
}
__device__ __forceinline__ void ldsm2(uint32_t& r0, uint32_t& r1, uint32_t a) {
    asm volatile("ldmatrix.sync.aligned.m8n8.x2.shared.b16 {%0,%1}, [%2];"
                 : "=r"(r0), "=r"(r1) : "r"(a));
}
__device__ __forceinline__ void mma16816(float* d, const uint32_t* a, const uint32_t* b) {
    asm volatile(
        "mma.sync.aligned.m16n8k16.row.col.f32.bf16.bf16.f32 "
        "{%0,%1,%2,%3}, {%4,%5,%6,%7}, {%8,%9}, {%0,%1,%2,%3};"
        : "+f"(d[0]), "+f"(d[1]), "+f"(d[2]), "+f"(d[3])
        : "r"(a[0]), "r"(a[1]), "r"(a[2]), "r"(a[3]), "r"(b[0]), "r"(b[1]));
}
__device__ __forceinline__ void mma16816h(float* d, const uint32_t* a, const uint32_t* b) {
    asm volatile(
        "mma.sync.aligned.m16n8k16.row.col.f32.f16.f16.f32 "
        "{%0,%1,%2,%3}, {%4,%5,%6,%7}, {%8,%9}, {%0,%1,%2,%3};"
        : "+f"(d[0]), "+f"(d[1]), "+f"(d[2]), "+f"(d[3])
        : "r"(a[0]), "r"(a[1]), "r"(a[2]), "r"(a[3]), "r"(b[0]), "r"(b[1]));
}
__device__ __forceinline__ void split2(float a, float b, uint32_t& hi, uint32_t& lo) {
    __nv_bfloat16 ha = __float2bfloat16(a), hb = __float2bfloat16(b);
    __nv_bfloat16 la = __float2bfloat16(a - __bfloat162float(ha));
    __nv_bfloat16 lb = __float2bfloat16(b - __bfloat162float(hb));
    __nv_bfloat162 ph; ph.x = ha; ph.y = hb;
    __nv_bfloat162 pl; pl.x = la; pl.y = lb;
    hi = *reinterpret_cast<uint32_t*>(&ph);
    lo = *reinterpret_cast<uint32_t*>(&pl);
}
__device__ __forceinline__ uint32_t packh2(float a, float b) {
    __half2 t = __floats2half2_rn(a, b);
    return *reinterpret_cast<uint32_t*>(&t);
}
__device__ __forceinline__ float ex2(float x) {
    float y;
    asm("ex2.approx.ftz.f32 %0, %1;" : "=f"(y) : "f"(x));
    return y;
}

// ---------------------------------------------------------------------------
// HMMA bf16-split GEMM (unchanged — measured at mma.sync model peak)
// ---------------------------------------------------------------------------
__global__ __launch_bounds__(256) void gemm_mma(
    const __nv_bfloat16* __restrict__ Ahi, const __nv_bfloat16* __restrict__ Alo,
    const __nv_bfloat16* __restrict__ Bhi, const __nv_bfloat16* __restrict__ Blo,
    float* __restrict__ C)
{
    extern __shared__ __align__(1024) char sm_raw[];
    const uint32_t SMB = smem_u32(sm_raw);

    const int tid  = threadIdx.x;
    const int wid  = tid >> 5, lane = tid & 31;
    const int row0 = blockIdx.y * 128;
    const int col0 = blockIdx.x * 128;

    const int lr = tid >> 3;
    const int lc = tid & 7;
    uint32_t ldst[4];
    #pragma unroll
    for (int it = 0; it < 4; it++) {
        int r = lr + it * 32;
        ldst[it] = (uint32_t)r * 128u + (uint32_t)((lc ^ (r & 7)) << 4);
    }

    const int wm = (wid & 1) * 64;
    const int wn = (wid >> 1) * 32;
    const int arow = wm + (lane & 15);
    const int ahi  = lane >> 4;
    const int brow = wn + (lane & 7);
    const int bhi  = (lane >> 3) & 1;

    float acc[4][4][4];
    #pragma unroll
    for (int mf = 0; mf < 4; mf++)
        #pragma unroll
        for (int nf = 0; nf < 4; nf++)
            #pragma unroll
            for (int r = 0; r < 4; r++) acc[mf][nf][r] = 0.f;

    auto load_tile = [&](int i) {
        const int b  = i & 1;
        const int s  = i >> 5;
        const int kk = (i & 31) << 6;
        const __nv_bfloat16* As = (s == 2) ? Alo : Ahi;
        const __nv_bfloat16* Bs = (s == 1) ? Blo : Bhi;
        const uint32_t ab = SMB + b * 32768;
        const uint32_t bb = ab + 16384;
        #pragma unroll
        for (int it = 0; it < 4; it++) {
            int r = lr + it * 32;
            cpasync16(ab + ldst[it], As + (size_t)(row0 + r) * 2048 + kk + lc * 8);
            cpasync16(bb + ldst[it], Bs + (size_t)(col0 + r) * 2048 + kk + lc * 8);
        }
        cp_commit();
    };

    load_tile(0);

    #pragma unroll 1
    for (int i = 0; i < 96; i++) {
        if (i + 1 < 96) { load_tile(i + 1); cp_wait<1>(); }
        else            { cp_wait<0>(); }
        __syncthreads();

        const uint32_t ab = SMB + (i & 1) * 32768;
        const uint32_t bb = ab + 16384;

        #pragma unroll
        for (int ks = 0; ks < 4; ks++) {
            uint32_t afr[4][4], bfr[4][2];
            #pragma unroll
            for (int mf = 0; mf < 4; mf++) {
                int r = arow + mf * 16;
                uint32_t addr = ab + (uint32_t)r * 128u
                              + (uint32_t)(((ks * 2 + ahi) ^ (r & 7)) << 4);
                ldsm4(afr[mf][0], afr[mf][1], afr[mf][2], afr[mf][3], addr);
            }
            #pragma unroll
            for (int nf = 0; nf < 4; nf++) {
                int r = brow + nf * 8;
                uint32_t addr = bb + (uint32_t)r * 128u
                              + (uint32_t)(((ks * 2 + bhi) ^ (r & 7)) << 4);
                ldsm2(bfr[nf][0], bfr[nf][1], addr);
            }
            #pragma unroll
            for (int mf = 0; mf < 4; mf++)
                #pragma unroll
                for (int nf = 0; nf < 4; nf++)
                    mma16816(acc[mf][nf], afr[mf], bfr[nf]);
        }
        __syncthreads();
    }

    #pragma unroll
    for (int mf = 0; mf < 4; mf++) {
        int rA = row0 + wm + mf * 16 + (lane >> 2);
        #pragma unroll
        for (int nf = 0; nf < 4; nf++) {
            int cA = col0 + wn + nf * 8 + (lane & 3) * 2;
            float2 lo = make_float2(acc[mf][nf][0], acc[mf][nf][1]);
            float2 hi = make_float2(acc[mf][nf][2], acc[mf][nf][3]);
            *(float2*)(C + (size_t)rA * 2048 + cA)       = lo;
            *(float2*)(C + (size_t)(rA + 8) * 2048 + cA) = hi;
        }
    }
}

// ---------------------------------------------------------------------------
// fp32 -> (bf16 hi, bf16 lo) split (for X)
// ---------------------------------------------------------------------------
__global__ __launch_bounds__(256) void convert_split(
    const float* __restrict__ src, __nv_bfloat16* __restrict__ hi,
    __nv_bfloat16* __restrict__ lo, int n4)
{
    int idx = blockIdx.x * 256 + threadIdx.x;
    if (idx >= n4) return;
    float4 v = ((const float4*)src)[idx];
    uint32_t h0, l0, h1, l1;
    split2(v.x, v.y, h0, l0);
    split2(v.z, v.w, h1, l1);
    ((uint32_t*)hi)[2*idx]   = h0;
    ((uint32_t*)hi)[2*idx+1] = h1;
    ((uint32_t*)lo)[2*idx]   = l0;
    ((uint32_t*)lo)[2*idx+1] = l1;
}

// ---------------------------------------------------------------------------
// Weight transpose + split: W[K][N] fp32 -> Whi/Wlo[N][K] bf16
// ---------------------------------------------------------------------------
__global__ __launch_bounds__(256) void convert_wt(
    const float* __restrict__ W, __nv_bfloat16* __restrict__ Whi,
    __nv_bfloat16* __restrict__ Wlo)
{
    __shared__ float t[32][33];
    int tx = threadIdx.x, ty = threadIdx.y;
    int kb = blockIdx.y * 32, nb = blockIdx.x * 32;
    #pragma unroll
    for (int it = 0; it < 4; it++)
        t[ty + it * 8][tx] = W[(size_t)(kb + ty + it * 8) * 2048 + nb + tx];
    __syncthreads();
    #pragma unroll
    for (int it = 0; it < 4; it++) {
        float x = t[tx][ty + it * 8];
        __nv_bfloat16 h = __float2bfloat16(x);
        __nv_bfloat16 l = __float2bfloat16(x - __bfloat162float(h));
        size_t o = (size_t)(nb + ty + it * 8) * 2048 + kb + tx;
        Whi[o] = h;
        Wlo[o] = l;
    }
}

// ---------------------------------------------------------------------------
// RoPE + scale(Q by 1/sqrt(HD)*log2e) + bf16 hi/lo split of Q and K
// ---------------------------------------------------------------------------
__global__ __launch_bounds__(256) void rope_split(const int* __restrict__ pos_ids)
{
    int idx = blockIdx.x * 256 + threadIdx.x;
    if (idx >= Bc * Sc * Hc * 64) return;
    int d = idx & 63;
    int h = (idx >> 6) & (Hc - 1);
    int t = idx >> 10;

    double inv = 1.0 / pow(10000.0, (double)(2 * d) / 128.0);
    float f = (float)((double)pos_ids[t] * inv);
    float sn, cs;
    sincosf(f, &sn, &cs);

    const float QS = 0.08838834764831845f * 1.4426950408889634f; // scale * log2(e)
    size_t base = (size_t)t * Dc + h * HDc + d;

    float q0 = g_q[base], q1 = g_q[base + 64];
    float r0 = (q0 * cs - q1 * sn) * QS;
    float r1 = (q1 * cs + q0 * sn) * QS;
    __nv_bfloat16 h0 = __float2bfloat16(r0), h1 = __float2bfloat16(r1);
    g_qhi[base]      = h0;
    g_qhi[base + 64] = h1;
    g_qlo[base]      = __float2bfloat16(r0 - __bfloat162float(h0));
    g_qlo[base + 64] = __float2bfloat16(r1 - __bfloat162float(h1));

    float k0 = g_k[base], k1 = g_k[base + 64];
    float s0 = k0 * cs - k1 * sn;
    float s1 = k1 * cs + k0 * sn;
    __nv_bfloat16 kh0 = __float2bfloat16(s0), kh1 = __float2bfloat16(s1);
    g_khi[base]      = kh0;
    g_khi[base + 64] = kh1;
    g_klo[base]      = __float2bfloat16(s0 - __bfloat162float(kh0));
    g_klo[base + 64] = __float2bfloat16(s1 - __bfloat162float(kh1));
}

// ---------------------------------------------------------------------------
// V transpose: g_v [b,s,h,hd] fp32 -> g_vth [b,h,hd,s] fp16
// ---------------------------------------------------------------------------
__global__ void vt_half()
{
    __shared__ float t[32][33];
    int tx = threadIdx.x, ty = threadIdx.y;
    int s0 = blockIdx.x * 32;
    int d0 = blockIdx.y * 32;
    int bh = blockIdx.z;
    int b = bh >> 4, h = bh & 15;
    #pragma unroll
    for (int it = 0; it < 4; it++)
        t[ty + it * 8][tx] =
            g_v[(size_t)(b * Sc + s0 + ty + it * 8) * Dc + h * HDc + d0 + tx];
    __syncthreads();
    #pragma unroll
    for (int it = 0; it < 4; it++) {
        float x = t[tx][ty + it * 8];
        size_t o = (size_t)((b * Hc + h) * HDc + d0 + ty + it * 8) * Sc + s0 + tx;
        g_vth[o] = __float2half_rn(x);
    }
}

// ---------------------------------------------------------------------------
// HMMA flash attention, causal. BQ=64 (4 warps x m16), BK=64, 128 threads,
// 112KB smem -> 2 CTAs/SM for cross-CTA pipe overlap.
// QK: bf16 3-pass split. PV: fp16 single pass (P,V fp16, f32 accum).
// K double-buffered (prefetch), V single-buffered (waited just before PV).
// ---------------------------------------------------------------------------
__global__ __launch_bounds__(128) void flash_mma(const int* __restrict__ amask)
{
    extern __shared__ char fsm[];
    const uint32_t SMB = smem_u32(fsm);
    __shared__ int msk[64];

    const int tid = threadIdx.x, wid = tid >> 5, lane = tid & 31;
    const int qb = gridDim.x - 1 - blockIdx.x;   // heavy tiles first
    const int h = blockIdx.y, b = blockIdx.z;

    const uint32_t KB0 = SMB + 32768;            // K bufs: 2 x (16KB hi + 16KB lo)
    const uint32_t VB  = SMB + 98304;            // V fp16: 128 x 128B = 16KB

    // ---- Q tiles (hi at SMB, lo at +16384): 64 rows x 256B, swizzled ----
    {
        const size_t qoff = (size_t)(b * Sc + qb * BQ) * Dc + h * HDc;
        #pragma unroll
        for (int it = 0; it < 16; it++) {
            int idx = tid + it * 128;            // 0..2047
            int s = idx >> 10;
            int r = (idx >> 4) & 63;
            int u = idx & 15;
            const __nv_bfloat16* src = (s ? g_qlo : g_qhi) + qoff + (size_t)r * Dc + u * 8;
            cpasync16(SMB + s * 16384 + (uint32_t)r * 256 + (uint32_t)((u ^ (r & 7)) << 4), src);
        }
    }
    cp_commit();                                 // group: Q

    const int nk = qb + 1;

    auto load_k = [&](int kb) {
        const uint32_t base = KB0 + (kb & 1) * 32768;
        const size_t koff = (size_t)(b * Sc + kb * BK) * Dc + h * HDc;
        #pragma unroll
        for (int it = 0; it < 16; it++) {
            int idx = tid + it * 128;
            int s = idx >> 10;
            int r = (idx >> 4) & 63;
            int u = idx & 15;
            const __nv_bfloat16* src = (s ? g_klo : g_khi) + koff + (size_t)r * Dc + u * 8;
            cpasync16(base + s * 16384 + (uint32_t)r * 256 + (uint32_t)((u ^ (r & 7)) << 4), src);
        }
    };
    auto load_v = [&](int kb) {
        const size_t voff = (size_t)((b * Hc + h) * HDc) * Sc + kb * BK;
        #pragma unroll
        for (int it = 0; it < 8; it++) {
            int idx = tid + it * 128;            // 0..1023
            int r = idx >> 3;                    // hd row 0..127
            int u = idx & 7;
            cpasync16(VB + (uint32_t)r * 128 + (uint32_t)((u ^ (r & 7)) << 4),
                      g_vth + voff + (size_t)r * Sc + u * 8);
        }
        if (tid < 64) msk[tid] = amask[b * Sc + kb * BK + tid];
    };

    load_k(0);
    cp_commit();                                 // group: K0

    float O[16][4];
    #pragma unroll
    for (int nh = 0; nh < 16; nh++)
        #pragma unroll
        for (int r = 0; r < 4; r++) O[nh][r] = 0.f;
    float m0 = -1e30f, m1 = -1e30f, l0 = 0.f, l1 = 0.f;

    const int wq = wid * 16;
    const int ar = wq + (lane & 15);
    const int ahalf = lane >> 4;
    const int brr   = (lane & 7) | ((lane & 16) >> 1);
    const int bhalf = (lane >> 3) & 1;
    const int row0g = qb * BQ + wq + (lane >> 2);

    #pragma unroll 1
    for (int kb = 0; kb < nk; kb++) {
        load_v(kb);
        cp_commit();                             // group: V(kb)
        if (kb + 1 < nk) load_k(kb + 1);
        cp_commit();                             // group: K(kb+1) (or empty)
        cp_wait<2>();                            // K(kb) + Q complete
        __syncthreads();

        const uint32_t kbase = KB0 + (kb & 1) * 32768;

        // ---- scores: Q K^T, 3-way bf16 split ----
        float S[8][4];
        #pragma unroll
        for (int nf = 0; nf < 8; nf++)
            #pragma unroll
            for (int r = 0; r < 4; r++) S[nf][r] = 0.f;

        #pragma unroll
        for (int ks = 0; ks < 8; ks++) {
            uint32_t ah[4], al[4];
            uint32_t qu = (uint32_t)(((2 * ks + ahalf) ^ (ar & 7)) << 4);
            ldsm4(ah[0], ah[1], ah[2], ah[3], SMB + (uint32_t)ar * 256 + qu);
            ldsm4(al[0], al[1], al[2], al[3], SMB + 16384 + (uint32_t)ar * 256 + qu);
            #pragma unroll
            for (int np = 0; np < 4; np++) {
                int r = np * 16 + brr;
                uint32_t uo = (uint32_t)(((2 * ks + bhalf) ^ (r & 7)) << 4);
                uint32_t bh[4], bl[4];
                ldsm4(bh[0], bh[1], bh[2], bh[3], kbase + (uint32_t)r * 256 + uo);
                ldsm4(bl[0], bl[1], bl[2], bl[3], kbase + 16384 + (uint32_t)r * 256 + uo);
                mma16816(S[2*np],     ah, bh + 0);
                mma16816(S[2*np + 1], ah, bh + 2);
                mma16816(S[2*np],     ah, bl + 0);
                mma16816(S[2*np + 1], ah, bl + 2);
                mma16816(S[2*np],     al, bh + 0);
                mma16816(S[2*np + 1], al, bh + 2);
            }
        }

        // ---- mask (causal + padding) ----
        #pragma unroll
        for (int nf = 0; nf < 8; nf++) {
            int c0 = nf * 8 + (lane & 3) * 2;
            int g0 = kb * BK + c0;
            bool k0 = msk[c0] != 0;
            bool k1 = msk[c0 + 1] != 0;
            if (!k0 || g0     > row0g)     S[nf][0] = -1e30f;
            if (!k1 || g0 + 1 > row0g)     S[nf][1] = -1e30f;
            if (!k0 || g0     > row0g + 8) S[nf][2] = -1e30f;
            if (!k1 || g0 + 1 > row0g + 8) S[nf][3] = -1e30f;
        }

        // ---- online softmax (base-2; log2e folded into Q scale) ----
        float mr0 = -1e30f, mr1 = -1e30f;
        #pragma unroll
        for (int nf = 0; nf < 8; nf++) {
            mr0 = fmaxf(mr0, fmaxf(S[nf][0], S[nf][1]));
            mr1 = fmaxf(mr1, fmaxf(S[nf][2], S[nf][3]));
        }
        mr0 = fmaxf(mr0, __shfl_xor_sync(0xffffffffu, mr0, 1));
        mr0 = fmaxf(mr0, __shfl_xor_sync(0xffffffffu, mr0, 2));
        mr1 = fmaxf(mr1, __shfl_xor_sync(0xffffffffu, mr1, 1));
        mr1 = fmaxf(mr1, __shfl_xor_sync(0xffffffffu, mr1, 2));
        float mn0 = fmaxf(m0, mr0), mn1 = fmaxf(m1, mr1);
        float f0 = ex2(m0 - mn0), f1 = ex2(m1 - mn1);

        uint32_t PH[4][4];
        float rs0 = 0.f, rs1 = 0.f;
        #pragma unroll
        for (int nf = 0; nf < 8; nf++) {
            float p0 = ex2(S[nf][0] - mn0);
            float p1 = ex2(S[nf][1] - mn0);
            float p2 = ex2(S[nf][2] - mn1);
            float p3 = ex2(S[nf][3] - mn1);
            rs0 += p0 + p1;
            rs1 += p2 + p3;
            int kp = nf >> 1, hv = (nf & 1) * 2;
            PH[kp][hv]     = packh2(p0, p1);
            PH[kp][hv + 1] = packh2(p2, p3);
        }
        rs0 += __shfl_xor_sync(0xffffffffu, rs0, 1);
        rs0 += __shfl_xor_sync(0xffffffffu, rs0, 2);
        rs1 += __shfl_xor_sync(0xffffffffu, rs1, 1);
        rs1 += __shfl_xor_sync(0xffffffffu, rs1, 2);
        l0 = l0 * f0 + rs0;
        l1 = l1 * f1 + rs1;
        m0 = mn0; m1 = mn1;

        #pragma unroll
        for (int nh = 0; nh < 16; nh++) {
            O[nh][0] *= f0; O[nh][1] *= f0;
            O[nh][2] *= f1; O[nh][3] *= f1;
        }

        // ---- O += P V (fp16 single pass) ----
        cp_wait<1>();                            // V(kb) complete (K(kb+1) pending)
        __syncthreads();
        #pragma unroll
        for (int kp = 0; kp < 4; kp++) {
            #pragma unroll
            for (int nhp = 0; nhp < 8; nhp++) {
                int r = nhp * 16 + brr;
                uint32_t uo = (uint32_t)(((2 * kp + bhalf) ^ (r & 7)) << 4);
                uint32_t vh[4];
                ldsm4(vh[0], vh[1], vh[2], vh[3], VB + (uint32_t)r * 128 + uo);
                mma16816h(O[2*nhp],     PH[kp], vh + 0);
                mma16816h(O[2*nhp + 1], PH[kp], vh + 2);
            }
        }
        __syncthreads();                         // protect V buf + msk for next tile
    }

    // ---- epilogue: normalize, split to bf16 hi/lo, write to xhi/xlo ----
    float i0 = 1.f / l0, i1 = 1.f / l1;
    size_t base0 = (size_t)(b * Sc + row0g) * Dc + h * HDc + (lane & 3) * 2;
    #pragma unroll
    for (int nh = 0; nh < 16; nh++) {
        uint32_t h0, lo0, h1, lo1;
        split2(O[nh][0] * i0, O[nh][1] * i0, h0, lo0);
        split2(O[nh][2] * i1, O[nh][3] * i1, h1, lo1);
        size_t a0 = base0 + nh * 8;
        size_t a1 = a0 + (size_t)8 * Dc;
        *(uint32_t*)(g_xhi + a0) = h0;
        *(uint32_t*)(g_xlo + a0) = lo0;
        *(uint32_t*)(g_xhi + a1) = h1;
        *(uint32_t*)(g_xlo + a1) = lo1;
    }
}

// ---------------------------------------------------------------------------
extern "C" void kernel_launch(void* const* d_in, const int* in_sizes, int n_in,
                              void* d_out, int out_size)
{
    const float* X   = (const float*)d_in[0];
    const int*   am  = (const int*)  d_in[1];
    const int*   pos = (const int*)  d_in[2];
    const float* Wq  = (const float*)d_in[3];
    const float* Wk  = (const float*)d_in[4];
    const float* Wv  = (const float*)d_in[5];
    const float* Wo  = (const float*)d_in[6];
    float* out = (float*)d_out;

    float *qp, *kp, *vp;
    __nv_bfloat16 *xhi, *xlo, *whi, *wlo;
    cudaGetSymbolAddress((void**)&qp,  g_q);
    cudaGetSymbolAddress((void**)&kp,  g_k);
    cudaGetSymbolAddress((void**)&vp,  g_v);
    cudaGetSymbolAddress((void**)&xhi, g_xhi);
    cudaGetSymbolAddress((void**)&xlo, g_xlo);
    cudaGetSymbolAddress((void**)&whi, g_whi);
    cudaGetSymbolAddress((void**)&wlo, g_wlo);

    const size_t WSZ = (size_t)Dc * Dc;
    const int N4 = Bc * Sc * Dc / 4;

    convert_split<<<(N4 + 255) / 256, 256>>>(X, xhi, xlo, N4);
    dim3 wtg(64, 64), wtb(32, 8);
    convert_wt<<<wtg, wtb>>>(Wq, whi + 0 * WSZ, wlo + 0 * WSZ);
    convert_wt<<<wtg, wtb>>>(Wk, whi + 1 * WSZ, wlo + 1 * WSZ);
    convert_wt<<<wtg, wtb>>>(Wv, whi + 2 * WSZ, wlo + 2 * WSZ);
    convert_wt<<<wtg, wtb>>>(Wo, whi + 3 * WSZ, wlo + 3 * WSZ);

    const int GEMM_SMEM = 65536;
    cudaFuncSetAttribute(gemm_mma, cudaFuncAttributeMaxDynamicSharedMemorySize, GEMM_SMEM);
    dim3 gg(16, 32), gb(256);
    gemm_mma<<<gg, gb, GEMM_SMEM>>>(xhi, xlo, whi + 0 * WSZ, wlo + 0 * WSZ, qp);
    gemm_mma<<<gg, gb, GEMM_SMEM>>>(xhi, xlo, whi + 1 * WSZ, wlo + 1 * WSZ, kp);
    gemm_mma<<<gg, gb, GEMM_SMEM>>>(xhi, xlo, whi + 2 * WSZ, wlo + 2 * WSZ, vp);

    rope_split<<<(Bc * Sc * Hc * 64) / 256, 256>>>(pos);
    vt_half<<<dim3(64, 4, 32), dim3(32, 8)>>>();

    const int FLASH_SMEM = 114688;   // Q 32KB + K 2x32KB + V 16KB
    cudaFuncSetAttribute(flash_mma, cudaFuncAttributeMaxDynamicSharedMemorySize, FLASH_SMEM);
    flash_mma<<<dim3(Sc / BQ, Hc, Bc), 128, FLASH_SMEM>>>(am);

    gemm_mma<<<gg, gb, GEMM_SMEM>>>(xhi, xlo, whi + 3 * WSZ, wlo + 3 * WSZ, out);
}

// round 7
// speedup vs baseline: 5.3555x; 1.2633x over previous
#include <cuda_runtime.h>
#include <cuda_bf16.h>
#include <cuda_fp16.h>
#include <math.h>
#include <stdint.h>

#define Bc 2
#define Sc 2048
#define Dc 2048
#define Hc 16
#define HDc 128
#define BQ 64
#define BK 64

// Scratch (allocation-free rule: __device__ globals)
__device__ float g_q[Bc*Sc*Dc];
__device__ float g_k[Bc*Sc*Dc];
__device__ float g_v[Bc*Sc*Dc];
__device__ __half g_xh[Bc*Sc*Dc];     // activations fp16 hi
__device__ __half g_xl[Bc*Sc*Dc];     // activations fp16 lo (residual)
__device__ __half g_wh[4*Dc*Dc];      // weights fp16, transposed [N][K]
__device__ __half g_qh[Bc*Sc*Dc];     // Q fp16 hi (scaled, roped)
__device__ __half g_ql[Bc*Sc*Dc];     // Q fp16 lo
__device__ __half g_kh[Bc*Sc*Dc];     // K fp16 (single)
__device__ __half g_vth[Bc*Sc*Dc];    // V^T fp16: [b][h][hd][s]

// ---------------------------------------------------------------------------
// PTX helpers (baseline sm_80+ features only — target-portable)
// ---------------------------------------------------------------------------
__device__ __forceinline__ uint32_t smem_u32(const void* p) {
    uint32_t a;
    asm("{ .reg .u64 t; cvta.to.shared.u64 t, %1; cvt.u32.u64 %0, t; }" : "=r"(a) : "l"(p));
    return a;
}
__device__ __forceinline__ void cpasync16(uint32_t dst, const void* src) {
    asm volatile("cp.async.cg.shared.global [%0], [%1], 16;" :: "r"(dst), "l"(src));
}
__device__ __forceinline__ void cp_commit() {
    asm volatile("cp.async.commit_group;" ::: "memory");
}
template <int N>
__device__ __forceinline__ void cp_wait() {
    asm volatile("cp.async.wait_group %0;" :: "n"(N) : "memory");
}
__device__ __forceinline__ void ldsm4(uint32_t& r0, uint32_t& r1, uint32_t& r2,
                                      uint32_t& r3, uint32_t a) {
    asm volatile("ldmatrix.sync.aligned.m8n8.x4.shared.b16 {%0,%1,%2,%3}, [%4];"
                 : "=r"(r0), "=r"(r1), "=r"(r2), "=r"(r3) : "r"(a));
}
__device__ __forceinline__ void ldsm2(uint32_t& r0, uint32_t& r1, uint32_t a) {
    asm volatile("ldmatrix.sync.aligned.m8n8.x2.shared.b16 {%0,%1}, [%2];"
                 : "=r"(r0), "=r"(r1) : "r"(a));
}
__device__ __forceinline__ void mma16816h(float* d, const uint32_t* a, const uint32_t* b) {
    asm volatile(
        "mma.sync.aligned.m16n8k16.row.col.f32.f16.f16.f32 "
        "{%0,%1,%2,%3}, {%4,%5,%6,%7}, {%8,%9}, {%0,%1,%2,%3};"
        : "+f"(d[0]), "+f"(d[1]), "+f"(d[2]), "+f"(d[3])
        : "r"(a[0]), "r"(a[1]), "r"(a[2]), "r"(a[3]), "r"(b[0]), "r"(b[1]));
}
// split two floats into packed fp16x2 hi + lo parts
__device__ __forceinline__ void split2h(float a, float b, uint32_t& hi, uint32_t& lo) {
    __half ha = __float2half_rn(a), hb = __float2half_rn(b);
    __half la = __float2half_rn(a - __half2float(ha));
    __half lb = __float2half_rn(b - __half2float(hb));
    __half2 ph = __halves2half2(ha, hb);
    __half2 pl = __halves2half2(la, lb);
    hi = *reinterpret_cast<uint32_t*>(&ph);
    lo = *reinterpret_cast<uint32_t*>(&pl);
}
__device__ __forceinline__ uint32_t packh2(float a, float b) {
    __half2 t = __floats2half2_rn(a, b);
    return *reinterpret_cast<uint32_t*>(&t);
}
__device__ __forceinline__ float ex2(float x) {
    float y;
    asm("ex2.approx.ftz.f32 %0, %1;" : "=f"(y) : "f"(x));
    return y;
}

// ---------------------------------------------------------------------------
// HMMA fp16 2-pass GEMM: C[4096,2048] = A @ W with A = Ah + Al (fp16 split),
// W single-rounded fp16. C = Ah*Wh + Al*Wh (exact A, error only from W round).
// CTA 128x128, K-tile 64, 64 k-tiles (2 segments), cp.async double buffered.
// ---------------------------------------------------------------------------
__global__ __launch_bounds__(256) void gemm_mma(
    const __half* __restrict__ Ahi, const __half* __restrict__ Alo,
    const __half* __restrict__ Bh, float* __restrict__ C)
{
    extern __shared__ __align__(1024) char sm_raw[];
    const uint32_t SMB = smem_u32(sm_raw);

    const int tid  = threadIdx.x;
    const int wid  = tid >> 5, lane = tid & 31;
    const int row0 = blockIdx.y * 128;
    const int col0 = blockIdx.x * 128;

    const int lr = tid >> 3;
    const int lc = tid & 7;
    uint32_t ldst[4];
    #pragma unroll
    for (int it = 0; it < 4; it++) {
        int r = lr + it * 32;
        ldst[it] = (uint32_t)r * 128u + (uint32_t)((lc ^ (r & 7)) << 4);
    }

    const int wm = (wid & 1) * 64;
    const int wn = (wid >> 1) * 32;
    const int arow = wm + (lane & 15);
    const int ahi  = lane >> 4;
    const int brow = wn + (lane & 7);
    const int bhi  = (lane >> 3) & 1;

    float acc[4][4][4];
    #pragma unroll
    for (int mf = 0; mf < 4; mf++)
        #pragma unroll
        for (int nf = 0; nf < 4; nf++)
            #pragma unroll
            for (int r = 0; r < 4; r++) acc[mf][nf][r] = 0.f;

    auto load_tile = [&](int i) {
        const int b  = i & 1;
        const int s  = i >> 5;                 // 0: Ah, 1: Al
        const int kk = (i & 31) << 6;
        const __half* As = s ? Alo : Ahi;
        const uint32_t ab = SMB + b * 32768;
        const uint32_t bb = ab + 16384;
        #pragma unroll
        for (int it = 0; it < 4; it++) {
            int r = lr + it * 32;
            cpasync16(ab + ldst[it], As + (size_t)(row0 + r) * 2048 + kk + lc * 8);
            cpasync16(bb + ldst[it], Bh + (size_t)(col0 + r) * 2048 + kk + lc * 8);
        }
        cp_commit();
    };

    load_tile(0);

    #pragma unroll 1
    for (int i = 0; i < 64; i++) {
        if (i + 1 < 64) { load_tile(i + 1); cp_wait<1>(); }
        else            { cp_wait<0>(); }
        __syncthreads();

        const uint32_t ab = SMB + (i & 1) * 32768;
        const uint32_t bb = ab + 16384;

        #pragma unroll
        for (int ks = 0; ks < 4; ks++) {
            uint32_t afr[4][4], bfr[4][2];
            #pragma unroll
            for (int mf = 0; mf < 4; mf++) {
                int r = arow + mf * 16;
                uint32_t addr = ab + (uint32_t)r * 128u
                              + (uint32_t)(((ks * 2 + ahi) ^ (r & 7)) << 4);
                ldsm4(afr[mf][0], afr[mf][1], afr[mf][2], afr[mf][3], addr);
            }
            #pragma unroll
            for (int nf = 0; nf < 4; nf++) {
                int r = brow + nf * 8;
                uint32_t addr = bb + (uint32_t)r * 128u
                              + (uint32_t)(((ks * 2 + bhi) ^ (r & 7)) << 4);
                ldsm2(bfr[nf][0], bfr[nf][1], addr);
            }
            #pragma unroll
            for (int mf = 0; mf < 4; mf++)
                #pragma unroll
                for (int nf = 0; nf < 4; nf++)
                    mma16816h(acc[mf][nf], afr[mf], bfr[nf]);
        }
        __syncthreads();
    }

    #pragma unroll
    for (int mf = 0; mf < 4; mf++) {
        int rA = row0 + wm + mf * 16 + (lane >> 2);
        #pragma unroll
        for (int nf = 0; nf < 4; nf++) {
            int cA = col0 + wn + nf * 8 + (lane & 3) * 2;
            float2 lo = make_float2(acc[mf][nf][0], acc[mf][nf][1]);
            float2 hi = make_float2(acc[mf][nf][2], acc[mf][nf][3]);
            *(float2*)(C + (size_t)rA * 2048 + cA)       = lo;
            *(float2*)(C + (size_t)(rA + 8) * 2048 + cA) = hi;
        }
    }
}

// ---------------------------------------------------------------------------
// fp32 -> (fp16 hi, fp16 lo) split (for X)
// ---------------------------------------------------------------------------
__global__ __launch_bounds__(256) void convert_split(
    const float* __restrict__ src, __half* __restrict__ hi,
    __half* __restrict__ lo, int n4)
{
    int idx = blockIdx.x * 256 + threadIdx.x;
    if (idx >= n4) return;
    float4 v = ((const float4*)src)[idx];
    uint32_t h0, l0, h1, l1;
    split2h(v.x, v.y, h0, l0);
    split2h(v.z, v.w, h1, l1);
    ((uint32_t*)hi)[2*idx]   = h0;
    ((uint32_t*)hi)[2*idx+1] = h1;
    ((uint32_t*)lo)[2*idx]   = l0;
    ((uint32_t*)lo)[2*idx+1] = l1;
}

// ---------------------------------------------------------------------------
// Weight transpose: W[K][N] fp32 -> Wh[N][K] fp16 (single-rounded)
// ---------------------------------------------------------------------------
__global__ __launch_bounds__(256) void convert_wt(
    const float* __restrict__ W, __half* __restrict__ Wh)
{
    __shared__ float t[32][33];
    int tx = threadIdx.x, ty = threadIdx.y;
    int kb = blockIdx.y * 32, nb = blockIdx.x * 32;
    #pragma unroll
    for (int it = 0; it < 4; it++)
        t[ty + it * 8][tx] = W[(size_t)(kb + ty + it * 8) * 2048 + nb + tx];
    __syncthreads();
    #pragma unroll
    for (int it = 0; it < 4; it++) {
        float x = t[tx][ty + it * 8];
        Wh[(size_t)(nb + ty + it * 8) * 2048 + kb + tx] = __float2half_rn(x);
    }
}

// ---------------------------------------------------------------------------
// RoPE + scale(Q by 1/sqrt(HD)*log2e) + fp16 split Q, single fp16 K
// ---------------------------------------------------------------------------
__global__ __launch_bounds__(256) void rope_split(const int* __restrict__ pos_ids)
{
    int idx = blockIdx.x * 256 + threadIdx.x;
    if (idx >= Bc * Sc * Hc * 64) return;
    int d = idx & 63;
    int h = (idx >> 6) & (Hc - 1);
    int t = idx >> 10;

    double inv = 1.0 / pow(10000.0, (double)(2 * d) / 128.0);
    float f = (float)((double)pos_ids[t] * inv);
    float sn, cs;
    sincosf(f, &sn, &cs);

    const float QS = 0.08838834764831845f * 1.4426950408889634f; // scale * log2(e)
    size_t base = (size_t)t * Dc + h * HDc + d;

    float q0 = g_q[base], q1 = g_q[base + 64];
    float r0 = (q0 * cs - q1 * sn) * QS;
    float r1 = (q1 * cs + q0 * sn) * QS;
    __half h0 = __float2half_rn(r0), h1 = __float2half_rn(r1);
    g_qh[base]      = h0;
    g_qh[base + 64] = h1;
    g_ql[base]      = __float2half_rn(r0 - __half2float(h0));
    g_ql[base + 64] = __float2half_rn(r1 - __half2float(h1));

    float k0 = g_k[base], k1 = g_k[base + 64];
    g_kh[base]      = __float2half_rn(k0 * cs - k1 * sn);
    g_kh[base + 64] = __float2half_rn(k1 * cs + k0 * sn);
}

// ---------------------------------------------------------------------------
// V transpose: g_v [b,s,h,hd] fp32 -> g_vth [b,h,hd,s] fp16
// ---------------------------------------------------------------------------
__global__ void vt_half()
{
    __shared__ float t[32][33];
    int tx = threadIdx.x, ty = threadIdx.y;
    int s0 = blockIdx.x * 32;
    int d0 = blockIdx.y * 32;
    int bh = blockIdx.z;
    int b = bh >> 4, h = bh & 15;
    #pragma unroll
    for (int it = 0; it < 4; it++)
        t[ty + it * 8][tx] =
            g_v[(size_t)(b * Sc + s0 + ty + it * 8) * Dc + h * HDc + d0 + tx];
    __syncthreads();
    #pragma unroll
    for (int it = 0; it < 4; it++) {
        float x = t[tx][ty + it * 8];
        size_t o = (size_t)((b * Hc + h) * HDc + d0 + ty + it * 8) * Sc + s0 + tx;
        g_vth[o] = __float2half_rn(x);
    }
}

// ---------------------------------------------------------------------------
// HMMA flash attention, causal. BQ=64 (4 warps), BK=64, 128 threads.
// QK: fp16 2-pass (Q split, K single). PV: fp16 single pass. f32 accum.
// Smem 80KB -> 2 CTAs/SM. K double-buffered, V waited just before PV.
// ---------------------------------------------------------------------------
__global__ __launch_bounds__(128) void flash_mma(const int* __restrict__ amask)
{
    extern __shared__ char fsm[];
    const uint32_t SMB = smem_u32(fsm);
    __shared__ int msk[64];

    const int tid = threadIdx.x, wid = tid >> 5, lane = tid & 31;
    const int qb = gridDim.x - 1 - blockIdx.x;   // heavy tiles first
    const int h = blockIdx.y, b = blockIdx.z;

    const uint32_t QH = SMB;                     // 64 x 256B = 16KB
    const uint32_t QL = SMB + 16384;             // 16KB
    const uint32_t KB0 = SMB + 32768;            // 2 bufs x 16KB
    const uint32_t VB  = SMB + 65536;            // 128 x 128B = 16KB

    // ---- Q tiles (hi + lo fp16): 64 rows x 256B, swizzled ----
    {
        const size_t qoff = (size_t)(b * Sc + qb * BQ) * Dc + h * HDc;
        #pragma unroll
        for (int it = 0; it < 16; it++) {
            int idx = tid + it * 128;            // 0..2047
            int s = idx >> 10;
            int r = (idx >> 4) & 63;
            int u = idx & 15;
            const __half* src = (s ? g_ql : g_qh) + qoff + (size_t)r * Dc + u * 8;
            cpasync16(QH + s * 16384 + (uint32_t)r * 256 + (uint32_t)((u ^ (r & 7)) << 4), src);
        }
    }
    cp_commit();                                 // group: Q

    const int nk = qb + 1;

    auto load_k = [&](int kb) {
        const uint32_t base = KB0 + (kb & 1) * 16384;
        const size_t koff = (size_t)(b * Sc + kb * BK) * Dc + h * HDc;
        #pragma unroll
        for (int it = 0; it < 8; it++) {
            int idx = tid + it * 128;            // 0..1023
            int r = idx >> 4;                    // 0..63
            int u = idx & 15;
            cpasync16(base + (uint32_t)r * 256 + (uint32_t)((u ^ (r & 7)) << 4),
                      g_kh + koff + (size_t)r * Dc + u * 8);
        }
    };
    auto load_v = [&](int kb) {
        const size_t voff = (size_t)((b * Hc + h) * HDc) * Sc + kb * BK;
        #pragma unroll
        for (int it = 0; it < 8; it++) {
            int idx = tid + it * 128;            // 0..1023
            int r = idx >> 3;                    // hd row 0..127
            int u = idx & 7;
            cpasync16(VB + (uint32_t)r * 128 + (uint32_t)((u ^ (r & 7)) << 4),
                      g_vth + voff + (size_t)r * Sc + u * 8);
        }
        if (tid < 64) msk[tid] = amask[b * Sc + kb * BK + tid];
    };

    load_k(0);
    cp_commit();                                 // group: K0

    float O[16][4];
    #pragma unroll
    for (int nh = 0; nh < 16; nh++)
        #pragma unroll
        for (int r = 0; r < 4; r++) O[nh][r] = 0.f;
    float m0 = -1e30f, m1 = -1e30f, l0 = 0.f, l1 = 0.f;

    const int wq = wid * 16;
    const int ar = wq + (lane & 15);
    const int ahalf = lane >> 4;
    const int brr   = (lane & 7) | ((lane & 16) >> 1);
    const int bhalf = (lane >> 3) & 1;
    const int row0g = qb * BQ + wq + (lane >> 2);

    #pragma unroll 1
    for (int kb = 0; kb < nk; kb++) {
        load_v(kb);
        cp_commit();                             // group: V(kb)
        if (kb + 1 < nk) load_k(kb + 1);
        cp_commit();                             // group: K(kb+1) (or empty)
        cp_wait<2>();                            // K(kb) + Q complete
        __syncthreads();

        const uint32_t kbase = KB0 + (kb & 1) * 16384;

        // ---- scores: Q K^T, fp16 2-pass ----
        float S[8][4];
        #pragma unroll
        for (int nf = 0; nf < 8; nf++)
            #pragma unroll
            for (int r = 0; r < 4; r++) S[nf][r] = 0.f;

        #pragma unroll
        for (int ks = 0; ks < 8; ks++) {
            uint32_t ah[4], al[4];
            uint32_t qu = (uint32_t)(((2 * ks + ahalf) ^ (ar & 7)) << 4);
            ldsm4(ah[0], ah[1], ah[2], ah[3], QH + (uint32_t)ar * 256 + qu);
            ldsm4(al[0], al[1], al[2], al[3], QL + (uint32_t)ar * 256 + qu);
            #pragma unroll
            for (int np = 0; np < 4; np++) {
                int r = np * 16 + brr;
                uint32_t uo = (uint32_t)(((2 * ks + bhalf) ^ (r & 7)) << 4);
                uint32_t bh[4];
                ldsm4(bh[0], bh[1], bh[2], bh[3], kbase + (uint32_t)r * 256 + uo);
                mma16816h(S[2*np],     ah, bh + 0);
                mma16816h(S[2*np + 1], ah, bh + 2);
                mma16816h(S[2*np],     al, bh + 0);
                mma16816h(S[2*np + 1], al, bh + 2);
            }
        }

        // ---- mask (causal + padding) ----
        #pragma unroll
        for (int nf = 0; nf < 8; nf++) {
            int c0 = nf * 8 + (lane & 3) * 2;
            int g0 = kb * BK + c0;
            bool k0 = msk[c0] != 0;
            bool k1 = msk[c0 + 1] != 0;
            if (!k0 || g0     > row0g)     S[nf][0] = -1e30f;
            if (!k1 || g0 + 1 > row0g)     S[nf][1] = -1e30f;
            if (!k0 || g0     > row0g + 8) S[nf][2] = -1e30f;
            if (!k1 || g0 + 1 > row0g + 8) S[nf][3] = -1e30f;
        }

        // ---- online softmax (base-2; log2e folded into Q scale) ----
        float mr0 = -1e30f, mr1 = -1e30f;
        #pragma unroll
        for (int nf = 0; nf < 8; nf++) {
            mr0 = fmaxf(mr0, fmaxf(S[nf][0], S[nf][1]));
            mr1 = fmaxf(mr1, fmaxf(S[nf][2], S[nf][3]));
        }
        mr0 = fmaxf(mr0, __shfl_xor_sync(0xffffffffu, mr0, 1));
        mr0 = fmaxf(mr0, __shfl_xor_sync(0xffffffffu, mr0, 2));
        mr1 = fmaxf(mr1, __shfl_xor_sync(0xffffffffu, mr1, 1));
        mr1 = fmaxf(mr1, __shfl_xor_sync(0xffffffffu, mr1, 2));
        float mn0 = fmaxf(m0, mr0), mn1 = fmaxf(m1, mr1);
        float f0 = ex2(m0 - mn0), f1 = ex2(m1 - mn1);

        uint32_t PH[4][4];
        float rs0 = 0.f, rs1 = 0.f;
        #pragma unroll
        for (int nf = 0; nf < 8; nf++) {
            float p0 = ex2(S[nf][0] - mn0);
            float p1 = ex2(S[nf][1] - mn0);
            float p2 = ex2(S[nf][2] - mn1);
            float p3 = ex2(S[nf][3] - mn1);
            rs0 += p0 + p1;
            rs1 += p2 + p3;
            int kp = nf >> 1, hv = (nf & 1) * 2;
            PH[kp][hv]     = packh2(p0, p1);
            PH[kp][hv + 1] = packh2(p2, p3);
        }
        rs0 += __shfl_xor_sync(0xffffffffu, rs0, 1);
        rs0 += __shfl_xor_sync(0xffffffffu, rs0, 2);
        rs1 += __shfl_xor_sync(0xffffffffu, rs1, 1);
        rs1 += __shfl_xor_sync(0xffffffffu, rs1, 2);
        l0 = l0 * f0 + rs0;
        l1 = l1 * f1 + rs1;
        m0 = mn0; m1 = mn1;

        #pragma unroll
        for (int nh = 0; nh < 16; nh++) {
            O[nh][0] *= f0; O[nh][1] *= f0;
            O[nh][2] *= f1; O[nh][3] *= f1;
        }

        // ---- O += P V (fp16 single pass) ----
        cp_wait<1>();                            // V(kb) complete (K(kb+1) pending)
        __syncthreads();
        #pragma unroll
        for (int kp = 0; kp < 4; kp++) {
            #pragma unroll
            for (int nhp = 0; nhp < 8; nhp++) {
                int r = nhp * 16 + brr;
                uint32_t uo = (uint32_t)(((2 * kp + bhalf) ^ (r & 7)) << 4);
                uint32_t vh[4];
                ldsm4(vh[0], vh[1], vh[2], vh[3], VB + (uint32_t)r * 128 + uo);
                mma16816h(O[2*nhp],     PH[kp], vh + 0);
                mma16816h(O[2*nhp + 1], PH[kp], vh + 2);
            }
        }
        __syncthreads();                         // protect V buf + msk for next tile
    }

    // ---- epilogue: normalize, fp16 split, write to xh/xl ----
    float i0 = 1.f / l0, i1 = 1.f / l1;
    size_t base0 = (size_t)(b * Sc + row0g) * Dc + h * HDc + (lane & 3) * 2;
    #pragma unroll
    for (int nh = 0; nh < 16; nh++) {
        uint32_t h0, lo0, h1, lo1;
        split2h(O[nh][0] * i0, O[nh][1] * i0, h0, lo0);
        split2h(O[nh][2] * i1, O[nh][3] * i1, h1, lo1);
        size_t a0 = base0 + nh * 8;
        size_t a1 = a0 + (size_t)8 * Dc;
        *(uint32_t*)(g_xh + a0) = h0;
        *(uint32_t*)(g_xl + a0) = lo0;
        *(uint32_t*)(g_xh + a1) = h1;
        *(uint32_t*)(g_xl + a1) = lo1;
    }
}

// ---------------------------------------------------------------------------
extern "C" void kernel_launch(void* const* d_in, const int* in_sizes, int n_in,
                              void* d_out, int out_size)
{
    const float* X   = (const float*)d_in[0];
    const int*   am  = (const int*)  d_in[1];
    const int*   pos = (const int*)  d_in[2];
    const float* Wq  = (const float*)d_in[3];
    const float* Wk  = (const float*)d_in[4];
    const float* Wv  = (const float*)d_in[5];
    const float* Wo  = (const float*)d_in[6];
    float* out = (float*)d_out;

    float *qp, *kp, *vp;
    __half *xh, *xl, *wh;
    cudaGetSymbolAddress((void**)&qp, g_q);
    cudaGetSymbolAddress((void**)&kp, g_k);
    cudaGetSymbolAddress((void**)&vp, g_v);
    cudaGetSymbolAddress((void**)&xh, g_xh);
    cudaGetSymbolAddress((void**)&xl, g_xl);
    cudaGetSymbolAddress((void**)&wh, g_wh);

    const size_t WSZ = (size_t)Dc * Dc;
    const int N4 = Bc * Sc * Dc / 4;

    convert_split<<<(N4 + 255) / 256, 256>>>(X, xh, xl, N4);
    dim3 wtg(64, 64), wtb(32, 8);
    convert_wt<<<wtg, wtb>>>(Wq, wh + 0 * WSZ);
    convert_wt<<<wtg, wtb>>>(Wk, wh + 1 * WSZ);
    convert_wt<<<wtg, wtb>>>(Wv, wh + 2 * WSZ);
    convert_wt<<<wtg, wtb>>>(Wo, wh + 3 * WSZ);

    const int GEMM_SMEM = 65536;
    cudaFuncSetAttribute(gemm_mma, cudaFuncAttributeMaxDynamicSharedMemorySize, GEMM_SMEM);
    dim3 gg(16, 32), gb(256);
    gemm_mma<<<gg, gb, GEMM_SMEM>>>(xh, xl, wh + 0 * WSZ, qp);
    gemm_mma<<<gg, gb, GEMM_SMEM>>>(xh, xl, wh + 1 * WSZ, kp);
    gemm_mma<<<gg, gb, GEMM_SMEM>>>(xh, xl, wh + 2 * WSZ, vp);

    rope_split<<<(Bc * Sc * Hc * 64) / 256, 256>>>(pos);
    vt_half<<<dim3(64, 4, 32), dim3(32, 8)>>>();

    const int FLASH_SMEM = 81920;   // Q 32KB + K 2x16KB + V 16KB
    cudaFuncSetAttribute(flash_mma, cudaFuncAttributeMaxDynamicSharedMemorySize, FLASH_SMEM);
    flash_mma<<<dim3(Sc / BQ, Hc, Bc), 128, FLASH_SMEM>>>(am);

    gemm_mma<<<gg, gb, GEMM_SMEM>>>(xh, xl, wh + 3 * WSZ, out);
}

// round 8
// speedup vs baseline: 5.5889x; 1.0436x over previous
#include <cuda_runtime.h>
#include <cuda_bf16.h>
#include <cuda_fp16.h>
#include <math.h>
#include <stdint.h>

#define Bc 2
#define Sc 2048
#define Dc 2048
#define Hc 16
#define HDc 128
#define BQ 64
#define BK 128

// Scratch (allocation-free rule: __device__ globals)
__device__ float g_q[Bc*Sc*Dc];
__device__ float g_k[Bc*Sc*Dc];
__device__ float g_v[Bc*Sc*Dc];
__device__ __half g_xh[Bc*Sc*Dc];     // activations fp16 hi
__device__ __half g_xl[Bc*Sc*Dc];     // activations fp16 lo (residual)
__device__ __half g_wh[4*Dc*Dc];      // weights fp16, transposed [N][K]
__device__ __half g_qh[Bc*Sc*Dc];     // Q fp16 hi (scaled, roped)
__device__ __half g_ql[Bc*Sc*Dc];     // Q fp16 lo
__device__ __half g_kh[Bc*Sc*Dc];     // K fp16 (single)
__device__ __half g_vth[Bc*Sc*Dc];    // V^T fp16: [b][h][hd][s]

// ---------------------------------------------------------------------------
// PTX helpers (baseline sm_80+ features only — target-portable)
// ---------------------------------------------------------------------------
__device__ __forceinline__ uint32_t smem_u32(const void* p) {
    uint32_t a;
    asm("{ .reg .u64 t; cvta.to.shared.u64 t, %1; cvt.u32.u64 %0, t; }" : "=r"(a) : "l"(p));
    return a;
}
__device__ __forceinline__ void cpasync16(uint32_t dst, const void* src) {
    asm volatile("cp.async.cg.shared.global [%0], [%1], 16;" :: "r"(dst), "l"(src));
}
__device__ __forceinline__ void cp_commit() {
    asm volatile("cp.async.commit_group;" ::: "memory");
}
template <int N>
__device__ __forceinline__ void cp_wait() {
    asm volatile("cp.async.wait_group %0;" :: "n"(N) : "memory");
}
__device__ __forceinline__ void ldsm4(uint32_t& r0, uint32_t& r1, uint32_t& r2,
                                      uint32_t& r3, uint32_t a) {
    asm volatile("ldmatrix.sync.aligned.m8n8.x4.shared.b16 {%0,%1,%2,%3}, [%4];"
                 : "=r"(r0), "=r"(r1), "=r"(r2), "=r"(r3) : "r"(a));
}
__device__ __forceinline__ void ldsm2(uint32_t& r0, uint32_t& r1, uint32_t a) {
    asm volatile("ldmatrix.sync.aligned.m8n8.x2.shared.b16 {%0,%1}, [%2];"
                 : "=r"(r0), "=r"(r1) : "r"(a));
}
__device__ __forceinline__ void mma16816h(float* d, const uint32_t* a, const uint32_t* b) {
    asm volatile(
        "mma.sync.aligned.m16n8k16.row.col.f32.f16.f16.f32 "
        "{%0,%1,%2,%3}, {%4,%5,%6,%7}, {%8,%9}, {%0,%1,%2,%3};"
        : "+f"(d[0]), "+f"(d[1]), "+f"(d[2]), "+f"(d[3])
        : "r"(a[0]), "r"(a[1]), "r"(a[2]), "r"(a[3]), "r"(b[0]), "r"(b[1]));
}
// split two floats into packed fp16x2 hi + lo parts
__device__ __forceinline__ void split2h(float a, float b, uint32_t& hi, uint32_t& lo) {
    __half ha = __float2half_rn(a), hb = __float2half_rn(b);
    __half la = __float2half_rn(a - __half2float(ha));
    __half lb = __float2half_rn(b - __half2float(hb));
    __half2 ph = __halves2half2(ha, hb);
    __half2 pl = __halves2half2(la, lb);
    hi = *reinterpret_cast<uint32_t*>(&ph);
    lo = *reinterpret_cast<uint32_t*>(&pl);
}
__device__ __forceinline__ uint32_t packh2(float a, float b) {
    __half2 t = __floats2half2_rn(a, b);
    return *reinterpret_cast<uint32_t*>(&t);
}
__device__ __forceinline__ float ex2(float x) {
    float y;
    asm("ex2.approx.ftz.f32 %0, %1;" : "=f"(y) : "f"(x));
    return y;
}

// ---------------------------------------------------------------------------
// HMMA fp16 2-pass GEMM: C = (Ah + Al) @ Wh, fp32 accum. grid.z selects
// weight slice (B0 + z*Dc*Dc) and output (c0/c1/c2) -> one launch for QKV.
// ---------------------------------------------------------------------------
__global__ __launch_bounds__(256) void gemm_mma(
    const __half* __restrict__ Ahi, const __half* __restrict__ Alo,
    const __half* __restrict__ B0,
    float* __restrict__ c0, float* __restrict__ c1, float* __restrict__ c2)
{
    extern __shared__ __align__(1024) char sm_raw[];
    const uint32_t SMB = smem_u32(sm_raw);

    const int z = blockIdx.z;
    const __half* Bh = B0 + (size_t)z * Dc * Dc;
    float* C = (z == 0) ? c0 : ((z == 1) ? c1 : c2);

    const int tid  = threadIdx.x;
    const int wid  = tid >> 5, lane = tid & 31;
    const int row0 = blockIdx.y * 128;
    const int col0 = blockIdx.x * 128;

    const int lr = tid >> 3;
    const int lc = tid & 7;
    uint32_t ldst[4];
    #pragma unroll
    for (int it = 0; it < 4; it++) {
        int r = lr + it * 32;
        ldst[it] = (uint32_t)r * 128u + (uint32_t)((lc ^ (r & 7)) << 4);
    }

    const int wm = (wid & 1) * 64;
    const int wn = (wid >> 1) * 32;
    const int arow = wm + (lane & 15);
    const int ahi  = lane >> 4;
    const int brow = wn + (lane & 7);
    const int bhi  = (lane >> 3) & 1;

    float acc[4][4][4];
    #pragma unroll
    for (int mf = 0; mf < 4; mf++)
        #pragma unroll
        for (int nf = 0; nf < 4; nf++)
            #pragma unroll
            for (int r = 0; r < 4; r++) acc[mf][nf][r] = 0.f;

    auto load_tile = [&](int i) {
        const int b  = i & 1;
        const int s  = i >> 5;                 // 0: Ah, 1: Al
        const int kk = (i & 31) << 6;
        const __half* As = s ? Alo : Ahi;
        const uint32_t ab = SMB + b * 32768;
        const uint32_t bb = ab + 16384;
        #pragma unroll
        for (int it = 0; it < 4; it++) {
            int r = lr + it * 32;
            cpasync16(ab + ldst[it], As + (size_t)(row0 + r) * 2048 + kk + lc * 8);
            cpasync16(bb + ldst[it], Bh + (size_t)(col0 + r) * 2048 + kk + lc * 8);
        }
        cp_commit();
    };

    load_tile(0);

    #pragma unroll 1
    for (int i = 0; i < 64; i++) {
        if (i + 1 < 64) { load_tile(i + 1); cp_wait<1>(); }
        else            { cp_wait<0>(); }
        __syncthreads();

        const uint32_t ab = SMB + (i & 1) * 32768;
        const uint32_t bb = ab + 16384;

        #pragma unroll
        for (int ks = 0; ks < 4; ks++) {
            uint32_t afr[4][4], bfr[4][2];
            #pragma unroll
            for (int mf = 0; mf < 4; mf++) {
                int r = arow + mf * 16;
                uint32_t addr = ab + (uint32_t)r * 128u
                              + (uint32_t)(((ks * 2 + ahi) ^ (r & 7)) << 4);
                ldsm4(afr[mf][0], afr[mf][1], afr[mf][2], afr[mf][3], addr);
            }
            #pragma unroll
            for (int nf = 0; nf < 4; nf++) {
                int r = brow + nf * 8;
                uint32_t addr = bb + (uint32_t)r * 128u
                              + (uint32_t)(((ks * 2 + bhi) ^ (r & 7)) << 4);
                ldsm2(bfr[nf][0], bfr[nf][1], addr);
            }
            #pragma unroll
            for (int mf = 0; mf < 4; mf++)
                #pragma unroll
                for (int nf = 0; nf < 4; nf++)
                    mma16816h(acc[mf][nf], afr[mf], bfr[nf]);
        }
        __syncthreads();
    }

    #pragma unroll
    for (int mf = 0; mf < 4; mf++) {
        int rA = row0 + wm + mf * 16 + (lane >> 2);
        #pragma unroll
        for (int nf = 0; nf < 4; nf++) {
            int cA = col0 + wn + nf * 8 + (lane & 3) * 2;
            float2 lo = make_float2(acc[mf][nf][0], acc[mf][nf][1]);
            float2 hi = make_float2(acc[mf][nf][2], acc[mf][nf][3]);
            *(float2*)(C + (size_t)rA * 2048 + cA)       = lo;
            *(float2*)(C + (size_t)(rA + 8) * 2048 + cA) = hi;
        }
    }
}

// ---------------------------------------------------------------------------
// fp32 -> (fp16 hi, fp16 lo) split (for X)
// ---------------------------------------------------------------------------
__global__ __launch_bounds__(256) void convert_split(
    const float* __restrict__ src, __half* __restrict__ hi,
    __half* __restrict__ lo, int n4)
{
    int idx = blockIdx.x * 256 + threadIdx.x;
    if (idx >= n4) return;
    float4 v = ((const float4*)src)[idx];
    uint32_t h0, l0, h1, l1;
    split2h(v.x, v.y, h0, l0);
    split2h(v.z, v.w, h1, l1);
    ((uint32_t*)hi)[2*idx]   = h0;
    ((uint32_t*)hi)[2*idx+1] = h1;
    ((uint32_t*)lo)[2*idx]   = l0;
    ((uint32_t*)lo)[2*idx+1] = l1;
}

// ---------------------------------------------------------------------------
// Weight transpose (all 4 weights in one launch via grid.z):
// W[K][N] fp32 -> Wh[N][K] fp16
// ---------------------------------------------------------------------------
__global__ __launch_bounds__(256) void convert_wt(
    const float* __restrict__ W0, const float* __restrict__ W1,
    const float* __restrict__ W2, const float* __restrict__ W3,
    __half* __restrict__ Wh)
{
    __shared__ float t[32][33];
    int tx = threadIdx.x, ty = threadIdx.y;
    int kb = blockIdx.y * 32, nb = blockIdx.x * 32;
    int z = blockIdx.z;
    const float* W = (z == 0) ? W0 : ((z == 1) ? W1 : ((z == 2) ? W2 : W3));
    __half* dst = Wh + (size_t)z * Dc * Dc;
    #pragma unroll
    for (int it = 0; it < 4; it++)
        t[ty + it * 8][tx] = W[(size_t)(kb + ty + it * 8) * 2048 + nb + tx];
    __syncthreads();
    #pragma unroll
    for (int it = 0; it < 4; it++) {
        float x = t[tx][ty + it * 8];
        dst[(size_t)(nb + ty + it * 8) * 2048 + kb + tx] = __float2half_rn(x);
    }
}

// ---------------------------------------------------------------------------
// RoPE + scale(Q by 1/sqrt(HD)*log2e) + fp16 split Q, single fp16 K
// ---------------------------------------------------------------------------
__global__ __launch_bounds__(256) void rope_split(const int* __restrict__ pos_ids)
{
    int idx = blockIdx.x * 256 + threadIdx.x;
    if (idx >= Bc * Sc * Hc * 64) return;
    int d = idx & 63;
    int h = (idx >> 6) & (Hc - 1);
    int t = idx >> 10;

    double inv = 1.0 / pow(10000.0, (double)(2 * d) / 128.0);
    float f = (float)((double)pos_ids[t] * inv);
    float sn, cs;
    sincosf(f, &sn, &cs);

    const float QS = 0.08838834764831845f * 1.4426950408889634f; // scale * log2(e)
    size_t base = (size_t)t * Dc + h * HDc + d;

    float q0 = g_q[base], q1 = g_q[base + 64];
    float r0 = (q0 * cs - q1 * sn) * QS;
    float r1 = (q1 * cs + q0 * sn) * QS;
    __half h0 = __float2half_rn(r0), h1 = __float2half_rn(r1);
    g_qh[base]      = h0;
    g_qh[base + 64] = h1;
    g_ql[base]      = __float2half_rn(r0 - __half2float(h0));
    g_ql[base + 64] = __float2half_rn(r1 - __half2float(h1));

    float k0 = g_k[base], k1 = g_k[base + 64];
    g_kh[base]      = __float2half_rn(k0 * cs - k1 * sn);
    g_kh[base + 64] = __float2half_rn(k1 * cs + k0 * sn);
}

// ---------------------------------------------------------------------------
// V transpose: g_v [b,s,h,hd] fp32 -> g_vth [b,h,hd,s] fp16
// ---------------------------------------------------------------------------
__global__ void vt_half()
{
    __shared__ float t[32][33];
    int tx = threadIdx.x, ty = threadIdx.y;
    int s0 = blockIdx.x * 32;
    int d0 = blockIdx.y * 32;
    int bh = blockIdx.z;
    int b = bh >> 4, h = bh & 15;
    #pragma unroll
    for (int it = 0; it < 4; it++)
        t[ty + it * 8][tx] =
            g_v[(size_t)(b * Sc + s0 + ty + it * 8) * Dc + h * HDc + d0 + tx];
    __syncthreads();
    #pragma unroll
    for (int it = 0; it < 4; it++) {
        float x = t[tx][ty + it * 8];
        size_t o = (size_t)((b * Hc + h) * HDc + d0 + ty + it * 8) * Sc + s0 + tx;
        g_vth[o] = __float2half_rn(x);
    }
}

// ---------------------------------------------------------------------------
// HMMA flash attention, causal. BQ=64 (4 warps), BK=128, 128 threads.
// QK: fp16 2-pass (Q split, K single). PV: fp16 single pass. f32 accum.
// Smem 96KB (Q 32 + K 32 + V 32, single-buffered) -> 2 CTAs/SM; cross-CTA
// overlap hides load latency. Halved per-tile fixed costs vs BK=64.
// ---------------------------------------------------------------------------
__global__ __launch_bounds__(128) void flash_mma(const int* __restrict__ amask)
{
    extern __shared__ char fsm[];
    const uint32_t SMB = smem_u32(fsm);
    __shared__ int msk[BK];

    const int tid = threadIdx.x, wid = tid >> 5, lane = tid & 31;
    const int qb = gridDim.x - 1 - blockIdx.x;   // heavy tiles first
    const int h = blockIdx.y, b = blockIdx.z;

    const uint32_t QH = SMB;                     // 64 x 256B = 16KB
    const uint32_t QL = SMB + 16384;             // 16KB
    const uint32_t KB = SMB + 32768;             // 128 x 256B = 32KB
    const uint32_t VB = SMB + 65536;             // 128 x 256B = 32KB

    // ---- Q tiles (hi + lo fp16): 64 rows x 256B, swizzled ----
    {
        const size_t qoff = (size_t)(b * Sc + qb * BQ) * Dc + h * HDc;
        #pragma unroll
        for (int it = 0; it < 16; it++) {
            int idx = tid + it * 128;            // 0..2047
            int s = idx >> 10;
            int r = (idx >> 4) & 63;
            int u = idx & 15;
            const __half* src = (s ? g_ql : g_qh) + qoff + (size_t)r * Dc + u * 8;
            cpasync16(QH + s * 16384 + (uint32_t)r * 256 + (uint32_t)((u ^ (r & 7)) << 4), src);
        }
    }

    const int nk = (qb + 2) >> 1;                // ceil((qb+1)/2) BK=128 tiles

    auto load_kv = [&](int kb) {
        const size_t koff = (size_t)(b * Sc + kb * BK) * Dc + h * HDc;
        const size_t voff = (size_t)((b * Hc + h) * HDc) * Sc + kb * BK;
        #pragma unroll
        for (int it = 0; it < 16; it++) {        // K: 128 rows x 16 units
            int idx = tid + it * 128;
            int r = idx >> 4;
            int u = idx & 15;
            cpasync16(KB + (uint32_t)r * 256 + (uint32_t)((u ^ (r & 7)) << 4),
                      g_kh + koff + (size_t)r * Dc + u * 8);
        }
        #pragma unroll
        for (int it = 0; it < 16; it++) {        // V^T: 128 hd-rows x 256B (128 keys)
            int idx = tid + it * 128;
            int r = idx >> 4;
            int u = idx & 15;
            cpasync16(VB + (uint32_t)r * 256 + (uint32_t)((u ^ (r & 7)) << 4),
                      g_vth + voff + (size_t)r * Sc + u * 8);
        }
        msk[tid] = amask[b * Sc + kb * BK + tid];
    };

    float O[16][4];
    #pragma unroll
    for (int nh = 0; nh < 16; nh++)
        #pragma unroll
        for (int r = 0; r < 4; r++) O[nh][r] = 0.f;
    float m0 = -1e30f, m1 = -1e30f, l0 = 0.f, l1 = 0.f;

    const int wq = wid * 16;
    const int ar = wq + (lane & 15);
    const int ahalf = lane >> 4;
    const int brr   = (lane & 7) | ((lane & 16) >> 1);
    const int bhalf = (lane >> 3) & 1;
    const int row0g = qb * BQ + wq + (lane >> 2);

    #pragma unroll 1
    for (int kb = 0; kb < nk; kb++) {
        load_kv(kb);
        cp_commit();
        cp_wait<0>();                            // Q (first iter) + K/V complete
        __syncthreads();

        // ---- scores: Q K^T, fp16 2-pass ----
        float S[16][4];
        #pragma unroll
        for (int nf = 0; nf < 16; nf++)
            #pragma unroll
            for (int r = 0; r < 4; r++) S[nf][r] = 0.f;

        #pragma unroll
        for (int ks = 0; ks < 8; ks++) {
            uint32_t ah[4], al[4];
            uint32_t qu = (uint32_t)(((2 * ks + ahalf) ^ (ar & 7)) << 4);
            ldsm4(ah[0], ah[1], ah[2], ah[3], QH + (uint32_t)ar * 256 + qu);
            ldsm4(al[0], al[1], al[2], al[3], QL + (uint32_t)ar * 256 + qu);
            #pragma unroll
            for (int np = 0; np < 8; np++) {
                int r = np * 16 + brr;
                uint32_t uo = (uint32_t)(((2 * ks + bhalf) ^ (r & 7)) << 4);
                uint32_t bh[4];
                ldsm4(bh[0], bh[1], bh[2], bh[3], KB + (uint32_t)r * 256 + uo);
                mma16816h(S[2*np],     ah, bh + 0);
                mma16816h(S[2*np + 1], ah, bh + 2);
                mma16816h(S[2*np],     al, bh + 0);
                mma16816h(S[2*np + 1], al, bh + 2);
            }
        }

        // ---- mask (causal + padding) ----
        #pragma unroll
        for (int nf = 0; nf < 16; nf++) {
            int c0 = nf * 8 + (lane & 3) * 2;
            int g0 = kb * BK + c0;
            bool k0 = msk[c0] != 0;
            bool k1 = msk[c0 + 1] != 0;
            if (!k0 || g0     > row0g)     S[nf][0] = -1e30f;
            if (!k1 || g0 + 1 > row0g)     S[nf][1] = -1e30f;
            if (!k0 || g0     > row0g + 8) S[nf][2] = -1e30f;
            if (!k1 || g0 + 1 > row0g + 8) S[nf][3] = -1e30f;
        }

        // ---- online softmax (base-2; log2e folded into Q scale) ----
        float mr0 = -1e30f, mr1 = -1e30f;
        #pragma unroll
        for (int nf = 0; nf < 16; nf++) {
            mr0 = fmaxf(mr0, fmaxf(S[nf][0], S[nf][1]));
            mr1 = fmaxf(mr1, fmaxf(S[nf][2], S[nf][3]));
        }
        mr0 = fmaxf(mr0, __shfl_xor_sync(0xffffffffu, mr0, 1));
        mr0 = fmaxf(mr0, __shfl_xor_sync(0xffffffffu, mr0, 2));
        mr1 = fmaxf(mr1, __shfl_xor_sync(0xffffffffu, mr1, 1));
        mr1 = fmaxf(mr1, __shfl_xor_sync(0xffffffffu, mr1, 2));
        float mn0 = fmaxf(m0, mr0), mn1 = fmaxf(m1, mr1);
        float f0 = ex2(m0 - mn0), f1 = ex2(m1 - mn1);

        uint32_t PH[8][4];
        float rs0 = 0.f, rs1 = 0.f;
        #pragma unroll
        for (int nf = 0; nf < 16; nf++) {
            float p0 = ex2(S[nf][0] - mn0);
            float p1 = ex2(S[nf][1] - mn0);
            float p2 = ex2(S[nf][2] - mn1);
            float p3 = ex2(S[nf][3] - mn1);
            rs0 += p0 + p1;
            rs1 += p2 + p3;
            int kp = nf >> 1, hv = (nf & 1) * 2;
            PH[kp][hv]     = packh2(p0, p1);
            PH[kp][hv + 1] = packh2(p2, p3);
        }
        rs0 += __shfl_xor_sync(0xffffffffu, rs0, 1);
        rs0 += __shfl_xor_sync(0xffffffffu, rs0, 2);
        rs1 += __shfl_xor_sync(0xffffffffu, rs1, 1);
        rs1 += __shfl_xor_sync(0xffffffffu, rs1, 2);
        l0 = l0 * f0 + rs0;
        l1 = l1 * f1 + rs1;
        m0 = mn0; m1 = mn1;

        #pragma unroll
        for (int nh = 0; nh < 16; nh++) {
            O[nh][0] *= f0; O[nh][1] *= f0;
            O[nh][2] *= f1; O[nh][3] *= f1;
        }

        // ---- O += P V (fp16 single pass) ----
        #pragma unroll
        for (int kp = 0; kp < 8; kp++) {
            #pragma unroll
            for (int nhp = 0; nhp < 8; nhp++) {
                int r = nhp * 16 + brr;
                uint32_t uo = (uint32_t)(((2 * kp + bhalf) ^ (r & 7)) << 4);
                uint32_t vh[4];
                ldsm4(vh[0], vh[1], vh[2], vh[3], VB + (uint32_t)r * 256 + uo);
                mma16816h(O[2*nhp],     PH[kp], vh + 0);
                mma16816h(O[2*nhp + 1], PH[kp], vh + 2);
            }
        }
        __syncthreads();                         // protect K/V/msk for next tile
    }

    // ---- epilogue: normalize, fp16 split, write to xh/xl ----
    float i0 = 1.f / l0, i1 = 1.f / l1;
    size_t base0 = (size_t)(b * Sc + row0g) * Dc + h * HDc + (lane & 3) * 2;
    #pragma unroll
    for (int nh = 0; nh < 16; nh++) {
        uint32_t h0, lo0, h1, lo1;
        split2h(O[nh][0] * i0, O[nh][1] * i0, h0, lo0);
        split2h(O[nh][2] * i1, O[nh][3] * i1, h1, lo1);
        size_t a0 = base0 + nh * 8;
        size_t a1 = a0 + (size_t)8 * Dc;
        *(uint32_t*)(g_xh + a0) = h0;
        *(uint32_t*)(g_xl + a0) = lo0;
        *(uint32_t*)(g_xh + a1) = h1;
        *(uint32_t*)(g_xl + a1) = lo1;
    }
}

// ---------------------------------------------------------------------------
extern "C" void kernel_launch(void* const* d_in, const int* in_sizes, int n_in,
                              void* d_out, int out_size)
{
    const float* X   = (const float*)d_in[0];
    const int*   am  = (const int*)  d_in[1];
    const int*   pos = (const int*)  d_in[2];
    const float* Wq  = (const float*)d_in[3];
    const float* Wk  = (const float*)d_in[4];
    const float* Wv  = (const float*)d_in[5];
    const float* Wo  = (const float*)d_in[6];
    float* out = (float*)d_out;

    float *qp, *kp, *vp;
    __half *xh, *xl, *wh;
    cudaGetSymbolAddress((void**)&qp, g_q);
    cudaGetSymbolAddress((void**)&kp, g_k);
    cudaGetSymbolAddress((void**)&vp, g_v);
    cudaGetSymbolAddress((void**)&xh, g_xh);
    cudaGetSymbolAddress((void**)&xl, g_xl);
    cudaGetSymbolAddress((void**)&wh, g_wh);

    const size_t WSZ = (size_t)Dc * Dc;
    const int N4 = Bc * Sc * Dc / 4;

    convert_split<<<(N4 + 255) / 256, 256>>>(X, xh, xl, N4);
    convert_wt<<<dim3(64, 64, 4), dim3(32, 8)>>>(Wq, Wk, Wv, Wo, wh);

    const int GEMM_SMEM = 65536;
    cudaFuncSetAttribute(gemm_mma, cudaFuncAttributeMaxDynamicSharedMemorySize, GEMM_SMEM);
    // fused QKV: grid.z selects weight + output
    gemm_mma<<<dim3(16, 32, 3), 256, GEMM_SMEM>>>(xh, xl, wh, qp, kp, vp);

    rope_split<<<(Bc * Sc * Hc * 64) / 256, 256>>>(pos);
    vt_half<<<dim3(64, 4, 32), dim3(32, 8)>>>();

    const int FLASH_SMEM = 98304;   // Q 32KB + K 32KB + V 32KB
    cudaFuncSetAttribute(flash_mma, cudaFuncAttributeMaxDynamicSharedMemorySize, FLASH_SMEM);
    flash_mma<<<dim3(Sc / BQ, Hc, Bc), 128, FLASH_SMEM>>>(am);

    // Wo projection
    gemm_mma<<<dim3(16, 32, 1), 256, GEMM_SMEM>>>(xh, xl, wh + 3 * WSZ, out, out, out);
}

// round 9
// speedup vs baseline: 9.4906x; 1.6981x over previous
#include <cuda_runtime.h>
#include <cuda_bf16.h>
#include <cuda_fp16.h>
#include <math.h>
#include <stdint.h>

#define Bc 2
#define Sc 2048
#define Dc 2048
#define Hc 16
#define HDc 128
#define BQ 64
#define BK 128

// Scratch (allocation-free rule: __device__ globals)
__device__ float g_q[Bc*Sc*Dc];
__device__ float g_k[Bc*Sc*Dc];
__device__ float g_v[Bc*Sc*Dc];
__device__ float g_sc[2048*128];      // [pos][d]: sin at d, cos at 64+d
__device__ __half g_xh[Bc*Sc*Dc];     // activations fp16 hi
__device__ __half g_xl[Bc*Sc*Dc];     // activations fp16 lo (residual)
__device__ __half g_wh[4*Dc*Dc];      // weights fp16, transposed [N][K]
__device__ __half g_qh[Bc*Sc*Dc];     // Q fp16 hi (scaled, roped)
__device__ __half g_ql[Bc*Sc*Dc];     // Q fp16 lo
__device__ __half g_kh[Bc*Sc*Dc];     // K fp16 (single)
__device__ __half g_vth[Bc*Sc*Dc];    // V^T fp16: [b][h][hd][s]

// ---------------------------------------------------------------------------
// PTX helpers (baseline sm_80+ features only — target-portable)
// ---------------------------------------------------------------------------
__device__ __forceinline__ uint32_t smem_u32(const void* p) {
    uint32_t a;
    asm("{ .reg .u64 t; cvta.to.shared.u64 t, %1; cvt.u32.u64 %0, t; }" : "=r"(a) : "l"(p));
    return a;
}
__device__ __forceinline__ void cpasync16(uint32_t dst, const void* src) {
    asm volatile("cp.async.cg.shared.global [%0], [%1], 16;" :: "r"(dst), "l"(src));
}
__device__ __forceinline__ void cp_commit() {
    asm volatile("cp.async.commit_group;" ::: "memory");
}
template <int N>
__device__ __forceinline__ void cp_wait() {
    asm volatile("cp.async.wait_group %0;" :: "n"(N) : "memory");
}
__device__ __forceinline__ void ldsm4(uint32_t& r0, uint32_t& r1, uint32_t& r2,
                                      uint32_t& r3, uint32_t a) {
    asm volatile("ldmatrix.sync.aligned.m8n8.x4.shared.b16 {%0,%1,%2,%3}, [%4];"
                 : "=r"(r0), "=r"(r1), "=r"(r2), "=r"(r3) : "r"(a));
}
__device__ __forceinline__ void ldsm2(uint32_t& r0, uint32_t& r1, uint32_t a) {
    asm volatile("ldmatrix.sync.aligned.m8n8.x2.shared.b16 {%0,%1}, [%2];"
                 : "=r"(r0), "=r"(r1) : "r"(a));
}
__device__ __forceinline__ void mma16816h(float* d, const uint32_t* a, const uint32_t* b) {
    asm volatile(
        "mma.sync.aligned.m16n8k16.row.col.f32.f16.f16.f32 "
        "{%0,%1,%2,%3}, {%4,%5,%6,%7}, {%8,%9}, {%0,%1,%2,%3};"
        : "+f"(d[0]), "+f"(d[1]), "+f"(d[2]), "+f"(d[3])
        : "r"(a[0]), "r"(a[1]), "r"(a[2]), "r"(a[3]), "r"(b[0]), "r"(b[1]));
}
// split two floats into packed fp16x2 hi + lo parts
__device__ __forceinline__ void split2h(float a, float b, uint32_t& hi, uint32_t& lo) {
    __half ha = __float2half_rn(a), hb = __float2half_rn(b);
    __half la = __float2half_rn(a - __half2float(ha));
    __half lb = __float2half_rn(b - __half2float(hb));
    __half2 ph = __halves2half2(ha, hb);
    __half2 pl = __halves2half2(la, lb);
    hi = *reinterpret_cast<uint32_t*>(&ph);
    lo = *reinterpret_cast<uint32_t*>(&pl);
}
__device__ __forceinline__ uint32_t packh2(float a, float b) {
    __half2 t = __floats2half2_rn(a, b);
    return *reinterpret_cast<uint32_t*>(&t);
}
__device__ __forceinline__ float ex2(float x) {
    float y;
    asm("ex2.approx.ftz.f32 %0, %1;" : "=f"(y) : "f"(x));
    return y;
}

// ---------------------------------------------------------------------------
// HMMA fp16 2-pass GEMM: C = (Ah + Al) @ Wh, fp32 accum. grid.z selects
// weight slice (B0 + z*Dc*Dc) and output (c0/c1/c2) -> one launch for QKV.
// ---------------------------------------------------------------------------
__global__ __launch_bounds__(256) void gemm_mma(
    const __half* __restrict__ Ahi, const __half* __restrict__ Alo,
    const __half* __restrict__ B0,
    float* __restrict__ c0, float* __restrict__ c1, float* __restrict__ c2)
{
    extern __shared__ __align__(1024) char sm_raw[];
    const uint32_t SMB = smem_u32(sm_raw);

    const int z = blockIdx.z;
    const __half* Bh = B0 + (size_t)z * Dc * Dc;
    float* C = (z == 0) ? c0 : ((z == 1) ? c1 : c2);

    const int tid  = threadIdx.x;
    const int wid  = tid >> 5, lane = tid & 31;
    const int row0 = blockIdx.y * 128;
    const int col0 = blockIdx.x * 128;

    const int lr = tid >> 3;
    const int lc = tid & 7;
    uint32_t ldst[4];
    #pragma unroll
    for (int it = 0; it < 4; it++) {
        int r = lr + it * 32;
        ldst[it] = (uint32_t)r * 128u + (uint32_t)((lc ^ (r & 7)) << 4);
    }

    const int wm = (wid & 1) * 64;
    const int wn = (wid >> 1) * 32;
    const int arow = wm + (lane & 15);
    const int ahi  = lane >> 4;
    const int brow = wn + (lane & 7);
    const int bhi  = (lane >> 3) & 1;

    float acc[4][4][4];
    #pragma unroll
    for (int mf = 0; mf < 4; mf++)
        #pragma unroll
        for (int nf = 0; nf < 4; nf++)
            #pragma unroll
            for (int r = 0; r < 4; r++) acc[mf][nf][r] = 0.f;

    auto load_tile = [&](int i) {
        const int b  = i & 1;
        const int s  = i >> 5;                 // 0: Ah, 1: Al
        const int kk = (i & 31) << 6;
        const __half* As = s ? Alo : Ahi;
        const uint32_t ab = SMB + b * 32768;
        const uint32_t bb = ab + 16384;
        #pragma unroll
        for (int it = 0; it < 4; it++) {
            int r = lr + it * 32;
            cpasync16(ab + ldst[it], As + (size_t)(row0 + r) * 2048 + kk + lc * 8);
            cpasync16(bb + ldst[it], Bh + (size_t)(col0 + r) * 2048 + kk + lc * 8);
        }
        cp_commit();
    };

    load_tile(0);

    #pragma unroll 1
    for (int i = 0; i < 64; i++) {
        if (i + 1 < 64) { load_tile(i + 1); cp_wait<1>(); }
        else            { cp_wait<0>(); }
        __syncthreads();

        const uint32_t ab = SMB + (i & 1) * 32768;
        const uint32_t bb = ab + 16384;

        #pragma unroll
        for (int ks = 0; ks < 4; ks++) {
            uint32_t afr[4][4], bfr[4][2];
            #pragma unroll
            for (int mf = 0; mf < 4; mf++) {
                int r = arow + mf * 16;
                uint32_t addr = ab + (uint32_t)r * 128u
                              + (uint32_t)(((ks * 2 + ahi) ^ (r & 7)) << 4);
                ldsm4(afr[mf][0], afr[mf][1], afr[mf][2], afr[mf][3], addr);
            }
            #pragma unroll
            for (int nf = 0; nf < 4; nf++) {
                int r = brow + nf * 8;
                uint32_t addr = bb + (uint32_t)r * 128u
                              + (uint32_t)(((ks * 2 + bhi) ^ (r & 7)) << 4);
                ldsm2(bfr[nf][0], bfr[nf][1], addr);
            }
            #pragma unroll
            for (int mf = 0; mf < 4; mf++)
                #pragma unroll
                for (int nf = 0; nf < 4; nf++)
                    mma16816h(acc[mf][nf], afr[mf], bfr[nf]);
        }
        __syncthreads();
    }

    #pragma unroll
    for (int mf = 0; mf < 4; mf++) {
        int rA = row0 + wm + mf * 16 + (lane >> 2);
        #pragma unroll
        for (int nf = 0; nf < 4; nf++) {
            int cA = col0 + wn + nf * 8 + (lane & 3) * 2;
            float2 lo = make_float2(acc[mf][nf][0], acc[mf][nf][1]);
            float2 hi = make_float2(acc[mf][nf][2], acc[mf][nf][3]);
            *(float2*)(C + (size_t)rA * 2048 + cA)       = lo;
            *(float2*)(C + (size_t)(rA + 8) * 2048 + cA) = hi;
        }
    }
}

// ---------------------------------------------------------------------------
// fp32 -> (fp16 hi, fp16 lo) split (for X)
// ---------------------------------------------------------------------------
__global__ __launch_bounds__(256) void convert_split(
    const float* __restrict__ src, __half* __restrict__ hi,
    __half* __restrict__ lo, int n4)
{
    int idx = blockIdx.x * 256 + threadIdx.x;
    if (idx >= n4) return;
    float4 v = ((const float4*)src)[idx];
    uint32_t h0, l0, h1, l1;
    split2h(v.x, v.y, h0, l0);
    split2h(v.z, v.w, h1, l1);
    ((uint32_t*)hi)[2*idx]   = h0;
    ((uint32_t*)hi)[2*idx+1] = h1;
    ((uint32_t*)lo)[2*idx]   = l0;
    ((uint32_t*)lo)[2*idx+1] = l1;
}

// ---------------------------------------------------------------------------
// Weight transpose (all 4 weights in one launch via grid.z):
// W[K][N] fp32 -> Wh[N][K] fp16
// ---------------------------------------------------------------------------
__global__ __launch_bounds__(256) void convert_wt(
    const float* __restrict__ W0, const float* __restrict__ W1,
    const float* __restrict__ W2, const float* __restrict__ W3,
    __half* __restrict__ Wh)
{
    __shared__ float t[32][33];
    int tx = threadIdx.x, ty = threadIdx.y;
    int kb = blockIdx.y * 32, nb = blockIdx.x * 32;
    int z = blockIdx.z;
    const float* W = (z == 0) ? W0 : ((z == 1) ? W1 : ((z == 2) ? W2 : W3));
    __half* dst = Wh + (size_t)z * Dc * Dc;
    #pragma unroll
    for (int it = 0; it < 4; it++)
        t[ty + it * 8][tx] = W[(size_t)(kb + ty + it * 8) * 2048 + nb + tx];
    __syncthreads();
    #pragma unroll
    for (int it = 0; it < 4; it++) {
        float x = t[tx][ty + it * 8];
        dst[(size_t)(nb + ty + it * 8) * 2048 + kb + tx] = __float2half_rn(x);
    }
}

// ---------------------------------------------------------------------------
// sin/cos table: one entry per (pos, d) pair — the fp64 pow + sincosf
// transcendental work done ONCE (131k threads) instead of per (b,t,h,d).
// ---------------------------------------------------------------------------
__global__ __launch_bounds__(256) void sc_table()
{
    int idx = blockIdx.x * 256 + threadIdx.x;
    if (idx >= 2048 * 64) return;
    int d = idx & 63;
    int p = idx >> 6;
    double inv = 1.0 / pow(10000.0, (double)(2 * d) / 128.0);
    float f = (float)((double)p * inv);
    float sn, cs;
    sincosf(f, &sn, &cs);
    g_sc[p * 128 + d]      = sn;
    g_sc[p * 128 + 64 + d] = cs;
}

// ---------------------------------------------------------------------------
// RoPE (table-driven) + scale(Q by 1/sqrt(HD)*log2e) + fp16 split Q, fp16 K
// ---------------------------------------------------------------------------
__global__ __launch_bounds__(256) void rope_split(const int* __restrict__ pos_ids)
{
    int idx = blockIdx.x * 256 + threadIdx.x;
    if (idx >= Bc * Sc * Hc * 64) return;
    int d = idx & 63;
    int h = (idx >> 6) & (Hc - 1);
    int t = idx >> 10;

    int p = pos_ids[t];
    float sn = g_sc[p * 128 + d];
    float cs = g_sc[p * 128 + 64 + d];

    const float QS = 0.08838834764831845f * 1.4426950408889634f; // scale * log2(e)
    size_t base = (size_t)t * Dc + h * HDc + d;

    float q0 = g_q[base], q1 = g_q[base + 64];
    float r0 = (q0 * cs - q1 * sn) * QS;
    float r1 = (q1 * cs + q0 * sn) * QS;
    __half h0 = __float2half_rn(r0), h1 = __float2half_rn(r1);
    g_qh[base]      = h0;
    g_qh[base + 64] = h1;
    g_ql[base]      = __float2half_rn(r0 - __half2float(h0));
    g_ql[base + 64] = __float2half_rn(r1 - __half2float(h1));

    float k0 = g_k[base], k1 = g_k[base + 64];
    g_kh[base]      = __float2half_rn(k0 * cs - k1 * sn);
    g_kh[base + 64] = __float2half_rn(k1 * cs + k0 * sn);
}

// ---------------------------------------------------------------------------
// V transpose: g_v [b,s,h,hd] fp32 -> g_vth [b,h,hd,s] fp16
// ---------------------------------------------------------------------------
__global__ void vt_half()
{
    __shared__ float t[32][33];
    int tx = threadIdx.x, ty = threadIdx.y;
    int s0 = blockIdx.x * 32;
    int d0 = blockIdx.y * 32;
    int bh = blockIdx.z;
    int b = bh >> 4, h = bh & 15;
    #pragma unroll
    for (int it = 0; it < 4; it++)
        t[ty + it * 8][tx] =
            g_v[(size_t)(b * Sc + s0 + ty + it * 8) * Dc + h * HDc + d0 + tx];
    __syncthreads();
    #pragma unroll
    for (int it = 0; it < 4; it++) {
        float x = t[tx][ty + it * 8];
        size_t o = (size_t)((b * Hc + h) * HDc + d0 + ty + it * 8) * Sc + s0 + tx;
        g_vth[o] = __float2half_rn(x);
    }
}

// ---------------------------------------------------------------------------
// HMMA flash attention, causal. BQ=64 (4 warps), BK=128, 128 threads.
// QK: fp16 2-pass (Q split, K single). PV: fp16 single pass. f32 accum.
// Smem 96KB -> 2 CTAs/SM; cross-CTA overlap hides load latency.
// ---------------------------------------------------------------------------
__global__ __launch_bounds__(128) void flash_mma(const int* __restrict__ amask)
{
    extern __shared__ char fsm[];
    const uint32_t SMB = smem_u32(fsm);
    __shared__ int msk[BK];

    const int tid = threadIdx.x, wid = tid >> 5, lane = tid & 31;
    const int qb = gridDim.x - 1 - blockIdx.x;   // heavy tiles first
    const int h = blockIdx.y, b = blockIdx.z;

    const uint32_t QH = SMB;                     // 64 x 256B = 16KB
    const uint32_t QL = SMB + 16384;             // 16KB
    const uint32_t KB = SMB + 32768;             // 128 x 256B = 32KB
    const uint32_t VB = SMB + 65536;             // 128 x 256B = 32KB

    // ---- Q tiles (hi + lo fp16): 64 rows x 256B, swizzled ----
    {
        const size_t qoff = (size_t)(b * Sc + qb * BQ) * Dc + h * HDc;
        #pragma unroll
        for (int it = 0; it < 16; it++) {
            int idx = tid + it * 128;            // 0..2047
            int s = idx >> 10;
            int r = (idx >> 4) & 63;
            int u = idx & 15;
            const __half* src = (s ? g_ql : g_qh) + qoff + (size_t)r * Dc + u * 8;
            cpasync16(QH + s * 16384 + (uint32_t)r * 256 + (uint32_t)((u ^ (r & 7)) << 4), src);
        }
    }

    const int nk = (qb + 2) >> 1;                // ceil((qb+1)/2) BK=128 tiles

    auto load_kv = [&](int kb) {
        const size_t koff = (size_t)(b * Sc + kb * BK) * Dc + h * HDc;
        const size_t voff = (size_t)((b * Hc + h) * HDc) * Sc + kb * BK;
        #pragma unroll
        for (int it = 0; it < 16; it++) {        // K: 128 rows x 16 units
            int idx = tid + it * 128;
            int r = idx >> 4;
            int u = idx & 15;
            cpasync16(KB + (uint32_t)r * 256 + (uint32_t)((u ^ (r & 7)) << 4),
                      g_kh + koff + (size_t)r * Dc + u * 8);
        }
        #pragma unroll
        for (int it = 0; it < 16; it++) {        // V^T: 128 hd-rows x 256B (128 keys)
            int idx = tid + it * 128;
            int r = idx >> 4;
            int u = idx & 15;
            cpasync16(VB + (uint32_t)r * 256 + (uint32_t)((u ^ (r & 7)) << 4),
                      g_vth + voff + (size_t)r * Sc + u * 8);
        }
        msk[tid] = amask[b * Sc + kb * BK + tid];
    };

    float O[16][4];
    #pragma unroll
    for (int nh = 0; nh < 16; nh++)
        #pragma unroll
        for (int r = 0; r < 4; r++) O[nh][r] = 0.f;
    float m0 = -1e30f, m1 = -1e30f, l0 = 0.f, l1 = 0.f;

    const int wq = wid * 16;
    const int ar = wq + (lane & 15);
    const int ahalf = lane >> 4;
    const int brr   = (lane & 7) | ((lane & 16) >> 1);
    const int bhalf = (lane >> 3) & 1;
    const int row0g = qb * BQ + wq + (lane >> 2);

    #pragma unroll 1
    for (int kb = 0; kb < nk; kb++) {
        load_kv(kb);
        cp_commit();
        cp_wait<0>();                            // Q (first iter) + K/V complete
        __syncthreads();

        // ---- scores: Q K^T, fp16 2-pass ----
        float S[16][4];
        #pragma unroll
        for (int nf = 0; nf < 16; nf++)
            #pragma unroll
            for (int r = 0; r < 4; r++) S[nf][r] = 0.f;

        #pragma unroll
        for (int ks = 0; ks < 8; ks++) {
            uint32_t ah[4], al[4];
            uint32_t qu = (uint32_t)(((2 * ks + ahalf) ^ (ar & 7)) << 4);
            ldsm4(ah[0], ah[1], ah[2], ah[3], QH + (uint32_t)ar * 256 + qu);
            ldsm4(al[0], al[1], al[2], al[3], QL + (uint32_t)ar * 256 + qu);
            #pragma unroll
            for (int np = 0; np < 8; np++) {
                int r = np * 16 + brr;
                uint32_t uo = (uint32_t)(((2 * ks + bhalf) ^ (r & 7)) << 4);
                uint32_t bh[4];
                ldsm4(bh[0], bh[1], bh[2], bh[3], KB + (uint32_t)r * 256 + uo);
                mma16816h(S[2*np],     ah, bh + 0);
                mma16816h(S[2*np + 1], ah, bh + 2);
                mma16816h(S[2*np],     al, bh + 0);
                mma16816h(S[2*np + 1], al, bh + 2);
            }
        }

        // ---- mask (causal + padding) ----
        #pragma unroll
        for (int nf = 0; nf < 16; nf++) {
            int c0 = nf * 8 + (lane & 3) * 2;
            int g0 = kb * BK + c0;
            bool k0 = msk[c0] != 0;
            bool k1 = msk[c0 + 1] != 0;
            if (!k0 || g0     > row0g)     S[nf][0] = -1e30f;
            if (!k1 || g0 + 1 > row0g)     S[nf][1] = -1e30f;
            if (!k0 || g0     > row0g + 8) S[nf][2] = -1e30f;
            if (!k1 || g0 + 1 > row0g + 8) S[nf][3] = -1e30f;
        }

        // ---- online softmax (base-2; log2e folded into Q scale) ----
        float mr0 = -1e30f, mr1 = -1e30f;
        #pragma unroll
        for (int nf = 0; nf < 16; nf++) {
            mr0 = fmaxf(mr0, fmaxf(S[nf][0], S[nf][1]));
            mr1 = fmaxf(mr1, fmaxf(S[nf][2], S[nf][3]));
        }
        mr0 = fmaxf(mr0, __shfl_xor_sync(0xffffffffu, mr0, 1));
        mr0 = fmaxf(mr0, __shfl_xor_sync(0xffffffffu, mr0, 2));
        mr1 = fmaxf(mr1, __shfl_xor_sync(0xffffffffu, mr1, 1));
        mr1 = fmaxf(mr1, __shfl_xor_sync(0xffffffffu, mr1, 2));
        float mn0 = fmaxf(m0, mr0), mn1 = fmaxf(m1, mr1);
        float f0 = ex2(m0 - mn0), f1 = ex2(m1 - mn1);

        uint32_t PH[8][4];
        float rs0 = 0.f, rs1 = 0.f;
        #pragma unroll
        for (int nf = 0; nf < 16; nf++) {
            float p0 = ex2(S[nf][0] - mn0);
            float p1 = ex2(S[nf][1] - mn0);
            float p2 = ex2(S[nf][2] - mn1);
            float p3 = ex2(S[nf][3] - mn1);
            rs0 += p0 + p1;
            rs1 += p2 + p3;
            int kp = nf >> 1, hv = (nf & 1) * 2;
            PH[kp][hv]     = packh2(p0, p1);
            PH[kp][hv + 1] = packh2(p2, p3);
        }
        rs0 += __shfl_xor_sync(0xffffffffu, rs0, 1);
        rs0 += __shfl_xor_sync(0xffffffffu, rs0, 2);
        rs1 += __shfl_xor_sync(0xffffffffu, rs1, 1);
        rs1 += __shfl_xor_sync(0xffffffffu, rs1, 2);
        l0 = l0 * f0 + rs0;
        l1 = l1 * f1 + rs1;
        m0 = mn0; m1 = mn1;

        #pragma unroll
        for (int nh = 0; nh < 16; nh++) {
            O[nh][0] *= f0; O[nh][1] *= f0;
            O[nh][2] *= f1; O[nh][3] *= f1;
        }

        // ---- O += P V (fp16 single pass) ----
        #pragma unroll
        for (int kp = 0; kp < 8; kp++) {
            #pragma unroll
            for (int nhp = 0; nhp < 8; nhp++) {
                int r = nhp * 16 + brr;
                uint32_t uo = (uint32_t)(((2 * kp + bhalf) ^ (r & 7)) << 4);
                uint32_t vh[4];
                ldsm4(vh[0], vh[1], vh[2], vh[3], VB + (uint32_t)r * 256 + uo);
                mma16816h(O[2*nhp],     PH[kp], vh + 0);
                mma16816h(O[2*nhp + 1], PH[kp], vh + 2);
            }
        }
        __syncthreads();                         // protect K/V/msk for next tile
    }

    // ---- epilogue: normalize, fp16 split, write to xh/xl ----
    float i0 = 1.f / l0, i1 = 1.f / l1;
    size_t base0 = (size_t)(b * Sc + row0g) * Dc + h * HDc + (lane & 3) * 2;
    #pragma unroll
    for (int nh = 0; nh < 16; nh++) {
        uint32_t h0, lo0, h1, lo1;
        split2h(O[nh][0] * i0, O[nh][1] * i0, h0, lo0);
        split2h(O[nh][2] * i1, O[nh][3] * i1, h1, lo1);
        size_t a0 = base0 + nh * 8;
        size_t a1 = a0 + (size_t)8 * Dc;
        *(uint32_t*)(g_xh + a0) = h0;
        *(uint32_t*)(g_xl + a0) = lo0;
        *(uint32_t*)(g_xh + a1) = h1;
        *(uint32_t*)(g_xl + a1) = lo1;
    }
}

// ---------------------------------------------------------------------------
extern "C" void kernel_launch(void* const* d_in, const int* in_sizes, int n_in,
                              void* d_out, int out_size)
{
    const float* X   = (const float*)d_in[0];
    const int*   am  = (const int*)  d_in[1];
    const int*   pos = (const int*)  d_in[2];
    const float* Wq  = (const float*)d_in[3];
    const float* Wk  = (const float*)d_in[4];
    const float* Wv  = (const float*)d_in[5];
    const float* Wo  = (const float*)d_in[6];
    float* out = (float*)d_out;

    float *qp, *kp, *vp;
    __half *xh, *xl, *wh;
    cudaGetSymbolAddress((void**)&qp, g_q);
    cudaGetSymbolAddress((void**)&kp, g_k);
    cudaGetSymbolAddress((void**)&vp, g_v);
    cudaGetSymbolAddress((void**)&xh, g_xh);
    cudaGetSymbolAddress((void**)&xl, g_xl);
    cudaGetSymbolAddress((void**)&wh, g_wh);

    const size_t WSZ = (size_t)Dc * Dc;
    const int N4 = Bc * Sc * Dc / 4;

    sc_table<<<(2048 * 64) / 256, 256>>>();
    convert_split<<<(N4 + 255) / 256, 256>>>(X, xh, xl, N4);
    convert_wt<<<dim3(64, 64, 4), dim3(32, 8)>>>(Wq, Wk, Wv, Wo, wh);

    const int GEMM_SMEM = 65536;
    cudaFuncSetAttribute(gemm_mma, cudaFuncAttributeMaxDynamicSharedMemorySize, GEMM_SMEM);
    // fused QKV: grid.z selects weight + output
    gemm_mma<<<dim3(16, 32, 3), 256, GEMM_SMEM>>>(xh, xl, wh, qp, kp, vp);

    rope_split<<<(Bc * Sc * Hc * 64) / 256, 256>>>(pos);
    vt_half<<<dim3(64, 4, 32), dim3(32, 8)>>>();

    const int FLASH_SMEM = 98304;   // Q 32KB + K 32KB + V 32KB
    cudaFuncSetAttribute(flash_mma, cudaFuncAttributeMaxDynamicSharedMemorySize, FLASH_SMEM);
    flash_mma<<<dim3(Sc / BQ, Hc, Bc), 128, FLASH_SMEM>>>(am);

    // Wo projection
    gemm_mma<<<dim3(16, 32, 1), 256, GEMM_SMEM>>>(xh, xl, wh + 3 * WSZ, out, out, out);
}